// round 8
// baseline (speedup 1.0000x reference)
#include <cuda_runtime.h>
#include <math.h>

// ---------------------------------------------------------------------------
// NAM-LSS V2 fused kernel, v4b: R=8 rows/thread, 256 threads (8 warps),
// packed fp32 (fma.rn.f32x2). Halves weight smem-crossbar traffic vs v3.
// rbf/h tiles aliased (smem 169,216 B). Head restructured to per-row loop
// (lower register pressure / smaller compiled body than v4, which failed
// twice at container level without producing a kernel signal).
// ---------------------------------------------------------------------------

namespace {
constexpr int B_TOT  = 16384;
constexpr int F      = 64;
constexpr int NB     = 64;
constexpr int H1     = 128;
constexpr int H2     = 128;
constexpr int TM     = 64;     // batch rows per CTA
constexpr int R      = 8;      // rows per thread
constexpr int NTHR   = 256;    // 8 warps
constexpr float LN_EPS = 1e-5f;

constexpr int S_RBF = NB + 2;   // 66
constexpr int S_H   = H1 + 4;   // 132

constexpr int OFF_W1   = 0;                      // [NB][H1]  8192
constexpr int OFF_W2   = OFF_W1 + NB * H1;       // [H1][H2] 16384
constexpr int OFF_WR   = OFF_W2 + H1 * H2;       // [NB][H2]  8192
constexpr int OFF_VEC  = OFF_WR + NB * H2;       // b1,g1,be1,b2,g2,be2,br
constexpr int OFF_WSM  = OFF_VEC + 7 * 128;
constexpr int OFF_CEN  = OFF_WSM + 64;
constexpr int OFF_IW   = OFF_CEN + 64;
constexpr int OFF_SCR  = OFF_IW + 64;            // rbf [TM][66] / h [TM][132]
constexpr int SMEM_FLOATS = OFF_SCR + TM * S_H;
constexpr int SMEM_BYTES  = SMEM_FLOATS * 4;     // 169,216 B
}

typedef unsigned long long u64;

__device__ __forceinline__ void fma2(u64& d, u64 a, u64 b) {
    asm("fma.rn.f32x2 %0, %1, %2, %0;" : "+l"(d) : "l"(a), "l"(b));
}

__device__ __forceinline__ u64 pack2(float v) {
    u64 r;
    asm("mov.b64 %0, {%1, %1};" : "=l"(r) : "f"(v));
    return r;
}

__device__ __forceinline__ float2 unpack2(u64 v) {
    float2 f;
    asm("mov.b64 {%0, %1}, %2;" : "=f"(f.x), "=f"(f.y) : "l"(v));
    return f;
}

__device__ __forceinline__ float red32(float v) {
    v += __shfl_xor_sync(0xffffffffu, v, 1);
    v += __shfl_xor_sync(0xffffffffu, v, 2);
    v += __shfl_xor_sync(0xffffffffu, v, 4);
    v += __shfl_xor_sync(0xffffffffu, v, 8);
    v += __shfl_xor_sync(0xffffffffu, v, 16);
    return v;
}

__device__ __forceinline__ float gelu_exact(float v) {
    return 0.5f * v * (1.0f + erff(v * 0.70710678118654752f));
}

__device__ __forceinline__ float softplus_f(float v) {
    return (v > 20.0f) ? v : log1pf(expf(v));
}

__device__ __forceinline__ float clipf(float v, float lo, float hi) {
    return fminf(fmaxf(v, lo), hi);
}

__global__ void __launch_bounds__(NTHR, 1)
nam_kernel(const float* __restrict__ x,        // [B,F]
           const float* __restrict__ centers,  // [F,NB]
           const float* __restrict__ logw,     // [F,NB]
           const float* __restrict__ W1,       // [F,NB,H1]
           const float* __restrict__ b1,
           const float* __restrict__ g1,
           const float* __restrict__ be1,
           const float* __restrict__ W2,       // [F,H1,H2]
           const float* __restrict__ b2,
           const float* __restrict__ g2,
           const float* __restrict__ be2,
           const float* __restrict__ Wr,       // [F,NB,H2]
           const float* __restrict__ br,
           const float* __restrict__ att,      // [F]
           const float* __restrict__ bias,     // [H2]
           const float* __restrict__ Wpi,      // [H2,3]
           const float* __restrict__ bpi,
           const float* __restrict__ Wa,
           const float* __restrict__ ba,
           const float* __restrict__ Wb,
           const float* __restrict__ bb,
           float* __restrict__ out)            // [B]
{
    extern __shared__ float smem[];
    float* W1s   = smem + OFF_W1;
    float* W2s   = smem + OFF_W2;
    float* Wrs   = smem + OFF_WR;
    float* vecs  = smem + OFF_VEC;
    float* w_s   = smem + OFF_WSM;
    float* cen_s = smem + OFF_CEN;
    float* iw_s  = smem + OFF_IW;
    float* rbf_s = smem + OFF_SCR;   // [TM][S_RBF]  (phase 1)
    float* hbuf  = smem + OFF_SCR;   // [TM][S_H]    (phase 2, aliased)

    const int tid  = threadIdx.x;
    const int cg   = tid & 31;        // lane: 4 cols (2 f32x2 pairs)
    const int rg   = tid >> 5;        // warp: rows {rg+8k, k=0..7}
    const int col0 = cg * 4;
    const int base_row = blockIdx.x * TM;

    if (tid < F) {
        float m = -1e30f;
        for (int i = 0; i < F; ++i) m = fmaxf(m, att[i]);
        float s = 0.0f;
        for (int i = 0; i < F; ++i) s += expf(att[i] - m);
        w_s[tid] = expf(att[tid] - m) / s;
    }

    float agg[32];
#pragma unroll
    for (int j = 0; j < 32; ++j) agg[j] = 0.0f;

    for (int f = 0; f < F; ++f) {
        __syncthreads();   // prev feature's smem consumers done

        // ---- stage weights (LDG -> STS, 32 float4/thread) ----
        {
            const float4* s1 = (const float4*)(W1 + (size_t)f * NB * H1);
            const float4* s2 = (const float4*)(W2 + (size_t)f * H1 * H2);
            const float4* sr = (const float4*)(Wr + (size_t)f * NB * H2);
            float4* d1 = (float4*)W1s;
            float4* d2 = (float4*)W2s;
            float4* dr = (float4*)Wrs;
#pragma unroll
            for (int i = 0; i < (NB * H1) / 4 / NTHR; ++i)
                d1[tid + i * NTHR] = s1[tid + i * NTHR];
#pragma unroll
            for (int i = 0; i < (H1 * H2) / 4 / NTHR; ++i)
                d2[tid + i * NTHR] = s2[tid + i * NTHR];
#pragma unroll
            for (int i = 0; i < (NB * H2) / 4 / NTHR; ++i)
                dr[tid + i * NTHR] = sr[tid + i * NTHR];
        }
        if (tid < 128) {
            vecs[tid]         = b1 [f * H1 + tid];
            vecs[128 + tid]   = g1 [f * H1 + tid];
            vecs[256 + tid]   = be1[f * H1 + tid];
            vecs[384 + tid]   = b2 [f * H2 + tid];
            vecs[512 + tid]   = g2 [f * H2 + tid];
            vecs[640 + tid]   = be2[f * H2 + tid];
            vecs[768 + tid]   = br [f * H2 + tid];
        } else if (tid < 192) {
            int t = tid - 128;
            cen_s[t] = centers[f * NB + t];
            float lw = clipf(logw[f * NB + t], -5.0f, 5.0f);
            iw_s[t] = 1.0f / (expf(lw) + 0.1f);
        }
        __syncthreads();

        // ---- RBF: warp computes its 8 rows; lane does n = 2cg, 2cg+1 ----
        {
            int n0 = cg * 2;
            float c0 = cen_s[n0],  c1 = cen_s[n0 + 1];
            float i0 = iw_s[n0],   i1 = iw_s[n0 + 1];
#pragma unroll
            for (int k = 0; k < R; ++k) {
                int row = rg + 8 * k;
                float xv = clipf(__ldg(x + (size_t)(base_row + row) * F + f), -10.0f, 10.0f);
                float d0 = clipf((xv - c0) * i0, -10.0f, 10.0f);
                float d1v = clipf((xv - c1) * i1, -10.0f, 10.0f);
                float2 e;
                e.x = __expf(-0.5f * d0 * d0);
                e.y = __expf(-0.5f * d1v * d1v);
                *(float2*)(rbf_s + row * S_RBF + n0) = e;
            }
        }
        __syncwarp();

        // ---- GEMV1 + residual fused (packed f32x2), 8 rows/thread ----
        u64 acc2[16], accr2[16];
#pragma unroll
        for (int j = 0; j < 16; ++j) { acc2[j] = 0ull; accr2[j] = 0ull; }
        for (int n2 = 0; n2 < NB / 2; ++n2) {
            float2 rb[R];
#pragma unroll
            for (int k = 0; k < R; ++k)
                rb[k] = *(const float2*)(rbf_s + (rg + 8 * k) * S_RBF + n2 * 2);
#pragma unroll
            for (int t = 0; t < 2; ++t) {
                int n = n2 * 2 + t;
                ulonglong2 w1p = *(const ulonglong2*)(W1s + n * H1 + col0);
                ulonglong2 wrp = *(const ulonglong2*)(Wrs + n * H2 + col0);
#pragma unroll
                for (int k = 0; k < R; ++k) {
                    u64 rr = pack2(t ? rb[k].y : rb[k].x);
                    fma2(acc2 [k*2+0], rr, w1p.x);
                    fma2(acc2 [k*2+1], rr, w1p.y);
                    fma2(accr2[k*2+0], rr, wrp.x);
                    fma2(accr2[k*2+1], rr, wrp.y);
                }
            }
        }

        // all rbf reads done before hbuf overwrites aliased scratch
        __syncthreads();

        // ---- +b1, LN, gelu -> hbuf ----
#pragma unroll
        for (int k = 0; k < R; ++k) {
            float2 p0 = unpack2(acc2[k*2+0]);
            float2 p1 = unpack2(acc2[k*2+1]);
            float v0 = p0.x + vecs[col0 + 0];
            float v1 = p0.y + vecs[col0 + 1];
            float v2 = p1.x + vecs[col0 + 2];
            float v3 = p1.y + vecs[col0 + 3];
            float s1 = red32(v0 + v1 + v2 + v3);
            float s2 = red32(v0*v0 + v1*v1 + v2*v2 + v3*v3);
            float mu  = s1 * (1.0f / H1);
            float var = s2 * (1.0f / H1) - mu * mu;
            float inv = rsqrtf(var + LN_EPS);
            float4 hv;
            hv.x = gelu_exact((v0 - mu) * inv * vecs[128 + col0 + 0] + vecs[256 + col0 + 0]);
            hv.y = gelu_exact((v1 - mu) * inv * vecs[128 + col0 + 1] + vecs[256 + col0 + 1]);
            hv.z = gelu_exact((v2 - mu) * inv * vecs[128 + col0 + 2] + vecs[256 + col0 + 2]);
            hv.w = gelu_exact((v3 - mu) * inv * vecs[128 + col0 + 3] + vecs[256 + col0 + 3]);
            *(float4*)(hbuf + (rg + 8 * k) * S_H + col0) = hv;
        }
        __syncwarp();   // h rows warp-private from here

        // ---- GEMV2 (packed): h[128] @ W2[128,128] ----
        u64 accb[16];
#pragma unroll
        for (int j = 0; j < 16; ++j) accb[j] = 0ull;
        for (int i4 = 0; i4 < H1 / 4; ++i4) {
            float4 hv[R];
#pragma unroll
            for (int k = 0; k < R; ++k)
                hv[k] = *(const float4*)(hbuf + (rg + 8 * k) * S_H + i4 * 4);
#pragma unroll
            for (int t = 0; t < 4; ++t) {
                int i = i4 * 4 + t;
                ulonglong2 w2p = *(const ulonglong2*)(W2s + i * H2 + col0);
#pragma unroll
                for (int k = 0; k < R; ++k) {
                    float h = (t == 0) ? hv[k].x : (t == 1) ? hv[k].y : (t == 2) ? hv[k].z : hv[k].w;
                    u64 hh = pack2(h);
                    fma2(accb[k*2+0], hh, w2p.x);
                    fma2(accb[k*2+1], hh, w2p.y);
                }
            }
        }

        // ---- +b2, LN, gelu; stacked; agg += w[f]*stacked ----
        {
            float wf = w_s[f];
#pragma unroll
            for (int k = 0; k < R; ++k) {
                float2 p0 = unpack2(accb[k*2+0]);
                float2 p1 = unpack2(accb[k*2+1]);
                float v0 = p0.x + vecs[384 + col0 + 0];
                float v1 = p0.y + vecs[384 + col0 + 1];
                float v2 = p1.x + vecs[384 + col0 + 2];
                float v3 = p1.y + vecs[384 + col0 + 3];
                float s1 = red32(v0 + v1 + v2 + v3);
                float s2 = red32(v0*v0 + v1*v1 + v2*v2 + v3*v3);
                float mu  = s1 * (1.0f / H2);
                float var = s2 * (1.0f / H2) - mu * mu;
                float inv = rsqrtf(var + LN_EPS);
                float2 r0 = unpack2(accr2[k*2+0]);
                float2 r1 = unpack2(accr2[k*2+1]);
                float hv0 = gelu_exact((v0 - mu) * inv * vecs[512 + col0 + 0] + vecs[640 + col0 + 0]);
                float hv1 = gelu_exact((v1 - mu) * inv * vecs[512 + col0 + 1] + vecs[640 + col0 + 1]);
                float hv2 = gelu_exact((v2 - mu) * inv * vecs[512 + col0 + 2] + vecs[640 + col0 + 2]);
                float hv3 = gelu_exact((v3 - mu) * inv * vecs[512 + col0 + 3] + vecs[640 + col0 + 3]);
                agg[k*4+0] = fmaf(wf, hv0 + 0.1f * (r0.x + vecs[768 + col0 + 0]), agg[k*4+0]);
                agg[k*4+1] = fmaf(wf, hv1 + 0.1f * (r0.y + vecs[768 + col0 + 1]), agg[k*4+1]);
                agg[k*4+2] = fmaf(wf, hv2 + 0.1f * (r1.x + vecs[768 + col0 + 2]), agg[k*4+2]);
                agg[k*4+3] = fmaf(wf, hv3 + 0.1f * (r1.y + vecs[768 + col0 + 3]), agg[k*4+3]);
            }
        }
    }

    // ---- head: per-row loop (low register pressure) ----
    // Per k: 9 dot-product partials over this lane's 4 cols, warp-reduce,
    // lane 0 finishes the mixture and writes the row.
    float wp[12], wwa[12], wwb[12], bs4[4];
#pragma unroll
    for (int j = 0; j < 4; ++j) {
        int r = col0 + j;
        wp [j*3+0] = __ldg(Wpi + r * 3 + 0);
        wp [j*3+1] = __ldg(Wpi + r * 3 + 1);
        wp [j*3+2] = __ldg(Wpi + r * 3 + 2);
        wwa[j*3+0] = __ldg(Wa  + r * 3 + 0);
        wwa[j*3+1] = __ldg(Wa  + r * 3 + 1);
        wwa[j*3+2] = __ldg(Wa  + r * 3 + 2);
        wwb[j*3+0] = __ldg(Wb  + r * 3 + 0);
        wwb[j*3+1] = __ldg(Wb  + r * 3 + 1);
        wwb[j*3+2] = __ldg(Wb  + r * 3 + 2);
        bs4[j] = __ldg(bias + r);
    }
    float bpi0 = __ldg(bpi + 0), bpi1 = __ldg(bpi + 1), bpi2 = __ldg(bpi + 2);
    float ba0  = __ldg(ba + 0),  ba1  = __ldg(ba + 1),  ba2  = __ldg(ba + 2);
    float bb0  = __ldg(bb + 0),  bb1  = __ldg(bb + 1),  bb2  = __ldg(bb + 2);

    for (int k = 0; k < R; ++k) {
        float p0 = 0.f, p1 = 0.f, p2 = 0.f;
        float a0 = 0.f, a1 = 0.f, a2 = 0.f;
        float c0 = 0.f, c1 = 0.f, c2 = 0.f;
#pragma unroll
        for (int j = 0; j < 4; ++j) {
            float a = agg[k*4+j] + bs4[j];
            p0 = fmaf(a, wp [j*3+0], p0);
            p1 = fmaf(a, wp [j*3+1], p1);
            p2 = fmaf(a, wp [j*3+2], p2);
            a0 = fmaf(a, wwa[j*3+0], a0);
            a1 = fmaf(a, wwa[j*3+1], a1);
            a2 = fmaf(a, wwa[j*3+2], a2);
            c0 = fmaf(a, wwb[j*3+0], c0);
            c1 = fmaf(a, wwb[j*3+1], c1);
            c2 = fmaf(a, wwb[j*3+2], c2);
        }
        p0 = red32(p0); p1 = red32(p1); p2 = red32(p2);
        a0 = red32(a0); a1 = red32(a1); a2 = red32(a2);
        c0 = red32(c0); c1 = red32(c1); c2 = red32(c2);

        if (cg == 0) {
            float l0 = p0 + bpi0, l1 = p1 + bpi1, l2 = p2 + bpi2;
            float m = fmaxf(l0, fmaxf(l1, l2));
            float e0 = expf(l0 - m), e1 = expf(l1 - m), e2 = expf(l2 - m);
            float inv_es = 1.0f / (e0 + e1 + e2);
            float ak0 = clipf(softplus_f(a0 + ba0) + 1.01f, 1.01f, 100.0f);
            float ak1 = clipf(softplus_f(a1 + ba1) + 1.01f, 1.01f, 100.0f);
            float ak2 = clipf(softplus_f(a2 + ba2) + 1.01f, 1.01f, 100.0f);
            float bk0 = clipf(softplus_f(c0 + bb0) + 1.01f, 1.01f, 100.0f);
            float bk1 = clipf(softplus_f(c1 + bb1) + 1.01f, 1.01f, 100.0f);
            float bk2 = clipf(softplus_f(c2 + bb2) + 1.01f, 1.01f, 100.0f);
            float pred = (e0 * inv_es) * (ak0 / (ak0 + bk0))
                       + (e1 * inv_es) * (ak1 / (ak1 + bk1))
                       + (e2 * inv_es) * (ak2 / (ak2 + bk2));
            out[base_row + rg + 8 * k] = clipf(pred, 0.001f, 0.999f);
        }
    }
}

extern "C" void kernel_launch(void* const* d_in, const int* in_sizes, int n_in,
                              void* d_out, int out_size) {
    (void)in_sizes; (void)n_in; (void)out_size;
    cudaFuncSetAttribute(nam_kernel,
                         cudaFuncAttributeMaxDynamicSharedMemorySize, SMEM_BYTES);
    const float* x       = (const float*)d_in[0];
    const float* centers = (const float*)d_in[1];
    const float* logw    = (const float*)d_in[2];
    const float* W1      = (const float*)d_in[3];
    const float* b1      = (const float*)d_in[4];
    const float* g1      = (const float*)d_in[5];
    const float* be1     = (const float*)d_in[6];
    const float* W2      = (const float*)d_in[7];
    const float* b2      = (const float*)d_in[8];
    const float* g2      = (const float*)d_in[9];
    const float* be2     = (const float*)d_in[10];
    const float* Wr      = (const float*)d_in[11];
    const float* br      = (const float*)d_in[12];
    const float* att     = (const float*)d_in[13];
    const float* bias    = (const float*)d_in[14];
    const float* Wpi     = (const float*)d_in[15];
    const float* bpi     = (const float*)d_in[16];
    const float* Wa      = (const float*)d_in[17];
    const float* ba      = (const float*)d_in[18];
    const float* Wb      = (const float*)d_in[19];
    const float* bb      = (const float*)d_in[20];
    float* out = (float*)d_out;

    nam_kernel<<<B_TOT / TM, NTHR, SMEM_BYTES>>>(
        x, centers, logw, W1, b1, g1, be1, W2, b2, g2, be2, Wr, br,
        att, bias, Wpi, bpi, Wa, ba, Wb, bb, out);
}

// round 9
// speedup vs baseline: 1.1428x; 1.1428x over previous
#include <cuda_runtime.h>
#include <math.h>

// ---------------------------------------------------------------------------
// NAM-LSS V2 fused kernel, v5: TM=128 rows/CTA, 512 threads (16 warps),
// R=8 rows/thread, packed fp32 (fma.rn.f32x2).
// Combines v4b's halved weight-crossbar traffic (8 rows amortize each weight
// read) with v3's 16-warp latency hiding. Residual contribution folded into
// agg right after GEMV1 (exact algebraic split) so accr dies before GEMV2,
// fitting the 128-reg/thread cap at 512 threads. rbf/h scratch aliased and
// warp-private across phases -> __syncwarp only. smem = 200,960 B.
// ---------------------------------------------------------------------------

namespace {
constexpr int B_TOT  = 16384;
constexpr int F      = 64;
constexpr int NB     = 64;
constexpr int H1     = 128;
constexpr int H2     = 128;
constexpr int TM     = 128;    // batch rows per CTA
constexpr int R      = 8;      // rows per thread
constexpr int NTHR   = 512;    // 16 warps; warp rg owns rows {rg+16k}
constexpr float LN_EPS = 1e-5f;

constexpr int S_RBF = 64;      // rbf row stride (broadcast reads: no pad needed)
constexpr int S_H   = 128;     // h row stride

constexpr int OFF_W1   = 0;                      // [NB][H1]  8192 floats
constexpr int OFF_W2   = OFF_W1 + NB * H1;       // [H1][H2] 16384
constexpr int OFF_WR   = OFF_W2 + H1 * H2;       // [NB][H2]  8192
constexpr int OFF_VEC  = OFF_WR + NB * H2;       // b1,g1,be1,b2,g2,be2,br
constexpr int OFF_WSM  = OFF_VEC + 7 * 128;
constexpr int OFF_CEN  = OFF_WSM + 64;
constexpr int OFF_IW   = OFF_CEN + 64;
constexpr int OFF_SCR  = OFF_IW + 64;            // rbf [TM][64] / h [TM][128]
constexpr int SMEM_FLOATS = OFF_SCR + TM * S_H;
constexpr int SMEM_BYTES  = SMEM_FLOATS * 4;     // 200,960 B
}

typedef unsigned long long u64;

__device__ __forceinline__ void fma2(u64& d, u64 a, u64 b) {
    asm("fma.rn.f32x2 %0, %1, %2, %0;" : "+l"(d) : "l"(a), "l"(b));
}

__device__ __forceinline__ u64 pack2(float v) {
    u64 r;
    asm("mov.b64 %0, {%1, %1};" : "=l"(r) : "f"(v));
    return r;
}

__device__ __forceinline__ float2 unpack2(u64 v) {
    float2 f;
    asm("mov.b64 {%0, %1}, %2;" : "=f"(f.x), "=f"(f.y) : "l"(v));
    return f;
}

__device__ __forceinline__ float red32(float v) {
    v += __shfl_xor_sync(0xffffffffu, v, 1);
    v += __shfl_xor_sync(0xffffffffu, v, 2);
    v += __shfl_xor_sync(0xffffffffu, v, 4);
    v += __shfl_xor_sync(0xffffffffu, v, 8);
    v += __shfl_xor_sync(0xffffffffu, v, 16);
    return v;
}

__device__ __forceinline__ float gelu_exact(float v) {
    return 0.5f * v * (1.0f + erff(v * 0.70710678118654752f));
}

__device__ __forceinline__ float softplus_f(float v) {
    return (v > 20.0f) ? v : log1pf(expf(v));
}

__device__ __forceinline__ float clipf(float v, float lo, float hi) {
    return fminf(fmaxf(v, lo), hi);
}

__global__ void __launch_bounds__(NTHR, 1)
nam_kernel(const float* __restrict__ x,        // [B,F]
           const float* __restrict__ centers,  // [F,NB]
           const float* __restrict__ logw,     // [F,NB]
           const float* __restrict__ W1,       // [F,NB,H1]
           const float* __restrict__ b1,
           const float* __restrict__ g1,
           const float* __restrict__ be1,
           const float* __restrict__ W2,       // [F,H1,H2]
           const float* __restrict__ b2,
           const float* __restrict__ g2,
           const float* __restrict__ be2,
           const float* __restrict__ Wr,       // [F,NB,H2]
           const float* __restrict__ br,
           const float* __restrict__ att,      // [F]
           const float* __restrict__ bias,     // [H2]
           const float* __restrict__ Wpi,      // [H2,3]
           const float* __restrict__ bpi,
           const float* __restrict__ Wa,
           const float* __restrict__ ba,
           const float* __restrict__ Wb,
           const float* __restrict__ bb,
           float* __restrict__ out)            // [B]
{
    extern __shared__ float smem[];
    float* W1s   = smem + OFF_W1;
    float* W2s   = smem + OFF_W2;
    float* Wrs   = smem + OFF_WR;
    float* vecs  = smem + OFF_VEC;
    float* w_s   = smem + OFF_WSM;
    float* cen_s = smem + OFF_CEN;
    float* iw_s  = smem + OFF_IW;
    float* rbf_s = smem + OFF_SCR;   // [TM][S_RBF]  (phase 1; warp-private rows)
    float* hbuf  = smem + OFF_SCR;   // [TM][S_H]    (phase 2, aliased)

    const int tid  = threadIdx.x;
    const int cg   = tid & 31;        // lane: 4 cols (2 f32x2 pairs)
    const int rg   = tid >> 5;        // warp: rows {rg+16k, k=0..7}
    const int col0 = cg * 4;
    const int base_row = blockIdx.x * TM;

    if (tid < F) {
        float m = -1e30f;
        for (int i = 0; i < F; ++i) m = fmaxf(m, att[i]);
        float s = 0.0f;
        for (int i = 0; i < F; ++i) s += expf(att[i] - m);
        w_s[tid] = expf(att[tid] - m) / s;
    }

    float agg[32];
#pragma unroll
    for (int j = 0; j < 32; ++j) agg[j] = 0.0f;

    for (int f = 0; f < F; ++f) {
        // guards: weight region overwrite vs all warps' reads of prev feature
        __syncthreads();

        // ---- stage weights (LDG -> STS, 16 float4/thread) ----
        {
            const float4* s1 = (const float4*)(W1 + (size_t)f * NB * H1);
            const float4* s2 = (const float4*)(W2 + (size_t)f * H1 * H2);
            const float4* sr = (const float4*)(Wr + (size_t)f * NB * H2);
            float4* d1 = (float4*)W1s;
            float4* d2 = (float4*)W2s;
            float4* dr = (float4*)Wrs;
#pragma unroll
            for (int i = 0; i < (NB * H1) / 4 / NTHR; ++i)
                d1[tid + i * NTHR] = s1[tid + i * NTHR];
#pragma unroll
            for (int i = 0; i < (H1 * H2) / 4 / NTHR; ++i)
                d2[tid + i * NTHR] = s2[tid + i * NTHR];
#pragma unroll
            for (int i = 0; i < (NB * H2) / 4 / NTHR; ++i)
                dr[tid + i * NTHR] = sr[tid + i * NTHR];
        }
        if (tid < 128) {
            vecs[tid]         = b1 [f * H1 + tid];
            vecs[128 + tid]   = g1 [f * H1 + tid];
            vecs[256 + tid]   = be1[f * H1 + tid];
            vecs[384 + tid]   = b2 [f * H2 + tid];
            vecs[512 + tid]   = g2 [f * H2 + tid];
            vecs[640 + tid]   = be2[f * H2 + tid];
            vecs[768 + tid]   = br [f * H2 + tid];
        } else if (tid >= 256 && tid < 320) {
            int t = tid - 256;
            cen_s[t] = centers[f * NB + t];
            float lw = clipf(logw[f * NB + t], -5.0f, 5.0f);
            iw_s[t] = 1.0f / (expf(lw) + 0.1f);
        }
        __syncthreads();

        // ---- RBF: warp computes its 8 rows; lane does n = 2cg, 2cg+1 ----
        // scratch rows {rg+16k} are private to warp rg in ALL phases.
        {
            int n0 = cg * 2;
            float c0 = cen_s[n0],  c1 = cen_s[n0 + 1];
            float i0 = iw_s[n0],   i1 = iw_s[n0 + 1];
#pragma unroll
            for (int k = 0; k < R; ++k) {
                int row = rg + 16 * k;
                float xv = clipf(__ldg(x + (size_t)(base_row + row) * F + f), -10.0f, 10.0f);
                float d0 = clipf((xv - c0) * i0, -10.0f, 10.0f);
                float d1v = clipf((xv - c1) * i1, -10.0f, 10.0f);
                float2 e;
                e.x = __expf(-0.5f * d0 * d0);
                e.y = __expf(-0.5f * d1v * d1v);
                *(float2*)(rbf_s + row * S_RBF + n0) = e;
            }
        }
        __syncwarp();

        // ---- GEMV1 + residual fused (packed f32x2), 8 rows/thread ----
        u64 acc2[16], accr2[16];
#pragma unroll
        for (int j = 0; j < 16; ++j) { acc2[j] = 0ull; accr2[j] = 0ull; }
        for (int n2 = 0; n2 < NB / 2; ++n2) {
            float2 rb[R];
#pragma unroll
            for (int k = 0; k < R; ++k)
                rb[k] = *(const float2*)(rbf_s + (rg + 16 * k) * S_RBF + n2 * 2);
#pragma unroll
            for (int t = 0; t < 2; ++t) {
                int n = n2 * 2 + t;
                ulonglong2 w1p = *(const ulonglong2*)(W1s + n * H1 + col0);
                ulonglong2 wrp = *(const ulonglong2*)(Wrs + n * H2 + col0);
#pragma unroll
                for (int k = 0; k < R; ++k) {
                    u64 rr = pack2(t ? rb[k].y : rb[k].x);
                    fma2(acc2 [k*2+0], rr, w1p.x);
                    fma2(acc2 [k*2+1], rr, w1p.y);
                    fma2(accr2[k*2+0], rr, wrp.x);
                    fma2(accr2[k*2+1], rr, wrp.y);
                }
            }
        }

        // ---- fold residual into agg NOW (frees accr before GEMV2):
        //      agg += wf*0.1*(res + br)  (h part added after GEMV2) ----
        {
            float wf01 = 0.1f * w_s[f];
#pragma unroll
            for (int k = 0; k < R; ++k) {
                float2 r0 = unpack2(accr2[k*2+0]);
                float2 r1 = unpack2(accr2[k*2+1]);
                agg[k*4+0] = fmaf(wf01, r0.x + vecs[768 + col0 + 0], agg[k*4+0]);
                agg[k*4+1] = fmaf(wf01, r0.y + vecs[768 + col0 + 1], agg[k*4+1]);
                agg[k*4+2] = fmaf(wf01, r1.x + vecs[768 + col0 + 2], agg[k*4+2]);
                agg[k*4+3] = fmaf(wf01, r1.y + vecs[768 + col0 + 3], agg[k*4+3]);
            }
        }
        __syncwarp();   // this warp's rbf reads done before hbuf overwrite

        // ---- +b1, LN, gelu -> hbuf (aliased scratch, warp-private rows) ----
#pragma unroll
        for (int k = 0; k < R; ++k) {
            float2 p0 = unpack2(acc2[k*2+0]);
            float2 p1 = unpack2(acc2[k*2+1]);
            float v0 = p0.x + vecs[col0 + 0];
            float v1 = p0.y + vecs[col0 + 1];
            float v2 = p1.x + vecs[col0 + 2];
            float v3 = p1.y + vecs[col0 + 3];
            float s1 = red32(v0 + v1 + v2 + v3);
            float s2 = red32(v0*v0 + v1*v1 + v2*v2 + v3*v3);
            float mu  = s1 * (1.0f / H1);
            float var = s2 * (1.0f / H1) - mu * mu;
            float inv = rsqrtf(var + LN_EPS);
            float4 hv;
            hv.x = gelu_exact((v0 - mu) * inv * vecs[128 + col0 + 0] + vecs[256 + col0 + 0]);
            hv.y = gelu_exact((v1 - mu) * inv * vecs[128 + col0 + 1] + vecs[256 + col0 + 1]);
            hv.z = gelu_exact((v2 - mu) * inv * vecs[128 + col0 + 2] + vecs[256 + col0 + 2]);
            hv.w = gelu_exact((v3 - mu) * inv * vecs[128 + col0 + 3] + vecs[256 + col0 + 3]);
            *(float4*)(hbuf + (rg + 16 * k) * S_H + col0) = hv;
        }
        __syncwarp();

        // ---- GEMV2 (packed): h[128] @ W2[128,128] ----
        u64 accb[16];
#pragma unroll
        for (int j = 0; j < 16; ++j) accb[j] = 0ull;
        for (int i4 = 0; i4 < H1 / 4; ++i4) {
            float4 hv[R];
#pragma unroll
            for (int k = 0; k < R; ++k)
                hv[k] = *(const float4*)(hbuf + (rg + 16 * k) * S_H + i4 * 4);
#pragma unroll
            for (int t = 0; t < 4; ++t) {
                int i = i4 * 4 + t;
                ulonglong2 w2p = *(const ulonglong2*)(W2s + i * H2 + col0);
#pragma unroll
                for (int k = 0; k < R; ++k) {
                    float h = (t == 0) ? hv[k].x : (t == 1) ? hv[k].y : (t == 2) ? hv[k].z : hv[k].w;
                    u64 hh = pack2(h);
                    fma2(accb[k*2+0], hh, w2p.x);
                    fma2(accb[k*2+1], hh, w2p.y);
                }
            }
        }

        // ---- +b2, LN, gelu; agg += wf*h2 ----
        {
            float wf = w_s[f];
#pragma unroll
            for (int k = 0; k < R; ++k) {
                float2 p0 = unpack2(accb[k*2+0]);
                float2 p1 = unpack2(accb[k*2+1]);
                float v0 = p0.x + vecs[384 + col0 + 0];
                float v1 = p0.y + vecs[384 + col0 + 1];
                float v2 = p1.x + vecs[384 + col0 + 2];
                float v3 = p1.y + vecs[384 + col0 + 3];
                float s1 = red32(v0 + v1 + v2 + v3);
                float s2 = red32(v0*v0 + v1*v1 + v2*v2 + v3*v3);
                float mu  = s1 * (1.0f / H2);
                float var = s2 * (1.0f / H2) - mu * mu;
                float inv = rsqrtf(var + LN_EPS);
                float hv0 = gelu_exact((v0 - mu) * inv * vecs[512 + col0 + 0] + vecs[640 + col0 + 0]);
                float hv1 = gelu_exact((v1 - mu) * inv * vecs[512 + col0 + 1] + vecs[640 + col0 + 1]);
                float hv2 = gelu_exact((v2 - mu) * inv * vecs[512 + col0 + 2] + vecs[640 + col0 + 2]);
                float hv3 = gelu_exact((v3 - mu) * inv * vecs[512 + col0 + 3] + vecs[640 + col0 + 3]);
                agg[k*4+0] = fmaf(wf, hv0, agg[k*4+0]);
                agg[k*4+1] = fmaf(wf, hv1, agg[k*4+1]);
                agg[k*4+2] = fmaf(wf, hv2, agg[k*4+2]);
                agg[k*4+3] = fmaf(wf, hv3, agg[k*4+3]);
            }
        }
    }

    // ---- head: per-row loop (low register pressure in main loop) ----
    for (int k = 0; k < R; ++k) {
        float p0 = 0.f, p1 = 0.f, p2 = 0.f;
        float a0 = 0.f, a1 = 0.f, a2 = 0.f;
        float c0 = 0.f, c1 = 0.f, c2 = 0.f;
#pragma unroll
        for (int j = 0; j < 4; ++j) {
            int r = col0 + j;
            float a = agg[k*4+j] + __ldg(bias + r);
            p0 = fmaf(a, __ldg(Wpi + r * 3 + 0), p0);
            p1 = fmaf(a, __ldg(Wpi + r * 3 + 1), p1);
            p2 = fmaf(a, __ldg(Wpi + r * 3 + 2), p2);
            a0 = fmaf(a, __ldg(Wa  + r * 3 + 0), a0);
            a1 = fmaf(a, __ldg(Wa  + r * 3 + 1), a1);
            a2 = fmaf(a, __ldg(Wa  + r * 3 + 2), a2);
            c0 = fmaf(a, __ldg(Wb  + r * 3 + 0), c0);
            c1 = fmaf(a, __ldg(Wb  + r * 3 + 1), c1);
            c2 = fmaf(a, __ldg(Wb  + r * 3 + 2), c2);
        }
        p0 = red32(p0); p1 = red32(p1); p2 = red32(p2);
        a0 = red32(a0); a1 = red32(a1); a2 = red32(a2);
        c0 = red32(c0); c1 = red32(c1); c2 = red32(c2);

        if (cg == 0) {
            float l0 = p0 + __ldg(bpi + 0);
            float l1 = p1 + __ldg(bpi + 1);
            float l2 = p2 + __ldg(bpi + 2);
            float m = fmaxf(l0, fmaxf(l1, l2));
            float e0 = expf(l0 - m), e1 = expf(l1 - m), e2 = expf(l2 - m);
            float inv_es = 1.0f / (e0 + e1 + e2);
            float ak0 = clipf(softplus_f(a0 + __ldg(ba + 0)) + 1.01f, 1.01f, 100.0f);
            float ak1 = clipf(softplus_f(a1 + __ldg(ba + 1)) + 1.01f, 1.01f, 100.0f);
            float ak2 = clipf(softplus_f(a2 + __ldg(ba + 2)) + 1.01f, 1.01f, 100.0f);
            float bk0 = clipf(softplus_f(c0 + __ldg(bb + 0)) + 1.01f, 1.01f, 100.0f);
            float bk1 = clipf(softplus_f(c1 + __ldg(bb + 1)) + 1.01f, 1.01f, 100.0f);
            float bk2 = clipf(softplus_f(c2 + __ldg(bb + 2)) + 1.01f, 1.01f, 100.0f);
            float pred = (e0 * inv_es) * (ak0 / (ak0 + bk0))
                       + (e1 * inv_es) * (ak1 / (ak1 + bk1))
                       + (e2 * inv_es) * (ak2 / (ak2 + bk2));
            out[base_row + rg + 16 * k] = clipf(pred, 0.001f, 0.999f);
        }
    }
}

extern "C" void kernel_launch(void* const* d_in, const int* in_sizes, int n_in,
                              void* d_out, int out_size) {
    (void)in_sizes; (void)n_in; (void)out_size;
    cudaFuncSetAttribute(nam_kernel,
                         cudaFuncAttributeMaxDynamicSharedMemorySize, SMEM_BYTES);
    const float* x       = (const float*)d_in[0];
    const float* centers = (const float*)d_in[1];
    const float* logw    = (const float*)d_in[2];
    const float* W1      = (const float*)d_in[3];
    const float* b1      = (const float*)d_in[4];
    const float* g1      = (const float*)d_in[5];
    const float* be1     = (const float*)d_in[6];
    const float* W2      = (const float*)d_in[7];
    const float* b2      = (const float*)d_in[8];
    const float* g2      = (const float*)d_in[9];
    const float* be2     = (const float*)d_in[10];
    const float* Wr      = (const float*)d_in[11];
    const float* br      = (const float*)d_in[12];
    const float* att     = (const float*)d_in[13];
    const float* bias    = (const float*)d_in[14];
    const float* Wpi     = (const float*)d_in[15];
    const float* bpi     = (const float*)d_in[16];
    const float* Wa      = (const float*)d_in[17];
    const float* ba      = (const float*)d_in[18];
    const float* Wb      = (const float*)d_in[19];
    const float* bb      = (const float*)d_in[20];
    float* out = (float*)d_out;

    nam_kernel<<<B_TOT / TM, NTHR, SMEM_BYTES>>>(
        x, centers, logw, W1, b1, g1, be1, W2, b2, g2, be2, Wr, br,
        att, bias, Wpi, bpi, Wa, ba, Wb, bb, out);
}

// round 10
// speedup vs baseline: 2.4749x; 2.1657x over previous
#include <cuda_runtime.h>
#include <math.h>

// ---------------------------------------------------------------------------
// NAM-LSS V2 fused kernel, v6: tf32 mma.sync (m16n8k8) fragment GEMMs.
// Grid 128 CTAs x 512 thr. CTA owns TM=128 rows; per feature:
//   stage weights (tf32-cvt, padded strides) -> rbf (tf32) ->
//   G3 (rbf@Wr, fold into agg) -> G1 (rbf@W1) -> LN1+gelu -> hbuf(tf32)
//   -> G2 (h@W2) -> LN2+gelu -> agg += w[f]*h2.
// Warp grid: 8 m-warps (16 rows) x 2 n-warps (64 cols). LN row stats cross
// the n-warp pair via smem. Accumulators/agg live in mma fragments.
// Strides: A-side 68/132 (=4 mod 32), B-side 136 (=8 mod 32) -> conflict-free.
// ---------------------------------------------------------------------------

namespace {
constexpr int B_TOT  = 16384;
constexpr int F      = 64;
constexpr int NB     = 64;
constexpr int H1     = 128;
constexpr int H2     = 128;
constexpr int TM     = 128;
constexpr int NTHR   = 512;    // 16 warps
constexpr float LN_EPS = 1e-5f;

constexpr int S_W = 136;   // weight smem row stride (floats), 136%32==8
constexpr int S_A = 68;    // rbf row stride, 68%32==4
constexpr int S_H = 132;   // hbuf row stride, 132%32==4

constexpr int OFF_W1   = 0;                       // [64][136]  8704
constexpr int OFF_W2   = OFF_W1 + NB * S_W;       // [128][136] 17408
constexpr int OFF_WR   = OFF_W2 + H1 * S_W;       // [64][136]  8704
constexpr int OFF_VEC  = OFF_WR + NB * S_W;       // 7*128
constexpr int OFF_WSM  = OFF_VEC + 7 * 128;       // 64
constexpr int OFF_CEN  = OFF_WSM + 64;
constexpr int OFF_IW   = OFF_CEN + 64;
constexpr int OFF_SCR  = OFF_IW + 64;             // rbf [128][68] / hbuf [128][132]
constexpr int SCR_FL   = TM * S_H;                // 16896 (hbuf is larger)
constexpr int OFF_LNR  = OFF_SCR + SCR_FL;        // float2 [128][2] -> 512 floats
constexpr int OFF_HR   = OFF_LNR + 512;           // [128][9] -> 1152
constexpr int SMEM_FLOATS = OFF_HR + 1152;
constexpr int SMEM_BYTES  = SMEM_FLOATS * 4;      // 217,856 B
}

__device__ __forceinline__ unsigned to_tf32(float f) {
    unsigned u;
    asm("cvt.rna.tf32.f32 %0, %1;" : "=r"(u) : "f"(f));
    return u;
}

__device__ __forceinline__ void mma8(float* d, const unsigned* a, unsigned b0, unsigned b1) {
    asm("mma.sync.aligned.m16n8k8.row.col.f32.tf32.tf32.f32 "
        "{%0,%1,%2,%3}, {%4,%5,%6,%7}, {%8,%9}, {%0,%1,%2,%3};"
        : "+f"(d[0]), "+f"(d[1]), "+f"(d[2]), "+f"(d[3])
        : "r"(a[0]), "r"(a[1]), "r"(a[2]), "r"(a[3]), "r"(b0), "r"(b1));
}

__device__ __forceinline__ float qred(float v) {   // reduce over 4-lane quad
    v += __shfl_xor_sync(0xffffffffu, v, 1);
    v += __shfl_xor_sync(0xffffffffu, v, 2);
    return v;
}

__device__ __forceinline__ float gelu_exact(float v) {
    return 0.5f * v * (1.0f + erff(v * 0.70710678118654752f));
}

__device__ __forceinline__ float softplus_f(float v) {
    return (v > 20.0f) ? v : log1pf(expf(v));
}

__device__ __forceinline__ float clipf(float v, float lo, float hi) {
    return fminf(fmaxf(v, lo), hi);
}

// One fragment GEMM phase: acc[8][4] += A[16 x 8K] @ W[8K x 64], tiles n0..n0+63.
__device__ __forceinline__ void gemm_frag(float acc[8][4], const unsigned* Abase, int sa,
                                          const unsigned* Wbase, int ksteps,
                                          int mrow0, int ncol0, int gid, int tidg) {
    for (int s = 0; s < ksteps; ++s) {
        unsigned a[4];
        const unsigned* ap = Abase + (mrow0 + gid) * sa + 8 * s + tidg;
        a[0] = ap[0];
        a[1] = ap[8 * sa];
        a[2] = ap[4];
        a[3] = ap[8 * sa + 4];
        const unsigned* bp  = Wbase + (8 * s + tidg) * S_W + ncol0 + gid;
        const unsigned* bp4 = bp + 4 * S_W;
#pragma unroll
        for (int nt = 0; nt < 8; ++nt)
            mma8(acc[nt], a, bp[8 * nt], bp4[8 * nt]);
    }
}

__global__ void __launch_bounds__(NTHR, 1)
nam_kernel(const float* __restrict__ x,        // [B,F]
           const float* __restrict__ centers,  // [F,NB]
           const float* __restrict__ logw,     // [F,NB]
           const float* __restrict__ W1,       // [F,NB,H1]
           const float* __restrict__ b1,
           const float* __restrict__ g1,
           const float* __restrict__ be1,
           const float* __restrict__ W2,       // [F,H1,H2]
           const float* __restrict__ b2,
           const float* __restrict__ g2,
           const float* __restrict__ be2,
           const float* __restrict__ Wr,       // [F,NB,H2]
           const float* __restrict__ br,
           const float* __restrict__ att,      // [F]
           const float* __restrict__ bias,     // [H2]
           const float* __restrict__ Wpi,      // [H2,3]
           const float* __restrict__ bpi,
           const float* __restrict__ Wa,
           const float* __restrict__ ba,
           const float* __restrict__ Wb,
           const float* __restrict__ bb,
           float* __restrict__ out)            // [B]
{
    extern __shared__ float smem[];
    unsigned* W1u   = (unsigned*)(smem + OFF_W1);
    unsigned* W2u   = (unsigned*)(smem + OFF_W2);
    unsigned* Wru   = (unsigned*)(smem + OFF_WR);
    float*    vecs  = smem + OFF_VEC;
    float*    w_s   = smem + OFF_WSM;
    float*    cen_s = smem + OFF_CEN;
    float*    iw_s  = smem + OFF_IW;
    unsigned* rbf_u = (unsigned*)(smem + OFF_SCR);   // [128][68]  (phase 1)
    unsigned* hbuf_u = (unsigned*)(smem + OFF_SCR);  // [128][132] (phase 2, aliased)
    float2*   lnred = (float2*)(smem + OFF_LNR);     // [row][nwid]
    float*    hred  = smem + OFF_HR;                 // [row][9]

    const int tid  = threadIdx.x;
    const int lane = tid & 31;
    const int wid  = tid >> 5;
    const int gid  = lane >> 2;     // 0..7
    const int tidg = lane & 3;      // 0..3
    const int mwid = wid & 7;       // m-warp: rows 16*mwid..+15
    const int nwid = wid >> 3;      // n-warp: cols 64*nwid..+63
    const int mrow0 = 16 * mwid;
    const int ncol0 = 64 * nwid;
    const int base_row = blockIdx.x * TM;

    if (tid < F) {
        float m = -1e30f;
        for (int i = 0; i < F; ++i) m = fmaxf(m, att[i]);
        float s = 0.0f;
        for (int i = 0; i < F; ++i) s += expf(att[i] - m);
        w_s[tid] = expf(att[tid] - m) / s;
    }

    float agg[8][4];
#pragma unroll
    for (int nt = 0; nt < 8; ++nt)
#pragma unroll
        for (int c = 0; c < 4; ++c) agg[nt][c] = 0.0f;

    for (int f = 0; f < F; ++f) {
        __syncthreads();   // all reads of prev feature's weights/vecs done

        // ---- stage weights with tf32 round + padded strides ----
        {
            const float4* s1 = (const float4*)(W1 + (size_t)f * NB * H1);
            const float4* s2 = (const float4*)(W2 + (size_t)f * H1 * H2);
            const float4* sr = (const float4*)(Wr + (size_t)f * NB * H2);
#pragma unroll
            for (int i = 0; i < 4; ++i) {
                int v = tid + i * NTHR;           // < 2048
                float4 w = s1[v];
                uint4 u = { to_tf32(w.x), to_tf32(w.y), to_tf32(w.z), to_tf32(w.w) };
                *(uint4*)(W1u + (v >> 5) * S_W + (v & 31) * 4) = u;
            }
#pragma unroll
            for (int i = 0; i < 8; ++i) {
                int v = tid + i * NTHR;           // < 4096
                float4 w = s2[v];
                uint4 u = { to_tf32(w.x), to_tf32(w.y), to_tf32(w.z), to_tf32(w.w) };
                *(uint4*)(W2u + (v >> 5) * S_W + (v & 31) * 4) = u;
            }
#pragma unroll
            for (int i = 0; i < 4; ++i) {
                int v = tid + i * NTHR;
                float4 w = sr[v];
                uint4 u = { to_tf32(w.x), to_tf32(w.y), to_tf32(w.z), to_tf32(w.w) };
                *(uint4*)(Wru + (v >> 5) * S_W + (v & 31) * 4) = u;
            }
        }
        if (tid < 128) {
            vecs[tid]         = b1 [f * H1 + tid];
            vecs[128 + tid]   = g1 [f * H1 + tid];
            vecs[256 + tid]   = be1[f * H1 + tid];
            vecs[384 + tid]   = b2 [f * H2 + tid];
            vecs[512 + tid]   = g2 [f * H2 + tid];
            vecs[640 + tid]   = be2[f * H2 + tid];
            vecs[768 + tid]   = br [f * H2 + tid];
        } else if (tid >= 256 && tid < 320) {
            int t = tid - 256;
            cen_s[t] = centers[f * NB + t];
            float lw = clipf(logw[f * NB + t], -5.0f, 5.0f);
            iw_s[t] = 1.0f / (expf(lw) + 0.1f);
        }
        __syncthreads();

        // ---- RBF: warp wid writes rows {wid+16k}; lane does cols 2l,2l+1 ----
        {
            int n0 = lane * 2;
            float c0 = cen_s[n0],  c1 = cen_s[n0 + 1];
            float i0 = iw_s[n0],   i1 = iw_s[n0 + 1];
#pragma unroll
            for (int k = 0; k < 8; ++k) {
                int row = wid + 16 * k;
                float xv = clipf(__ldg(x + (size_t)(base_row + row) * F + f), -10.0f, 10.0f);
                float d0 = clipf((xv - c0) * i0, -10.0f, 10.0f);
                float d1v = clipf((xv - c1) * i1, -10.0f, 10.0f);
                uint2 e;
                e.x = to_tf32(__expf(-0.5f * d0 * d0));
                e.y = to_tf32(__expf(-0.5f * d1v * d1v));
                *(uint2*)(rbf_u + row * S_A + n0) = e;
            }
        }
        __syncthreads();

        float acc[8][4];

        // ---- G3: res = rbf @ Wr ; fold into agg (agg += wf*0.1*(res+br)) ----
#pragma unroll
        for (int nt = 0; nt < 8; ++nt)
#pragma unroll
            for (int c = 0; c < 4; ++c) acc[nt][c] = 0.0f;
        gemm_frag(acc, rbf_u, S_A, Wru, NB / 8, mrow0, ncol0, gid, tidg);
        {
            float wf01 = 0.1f * w_s[f];
#pragma unroll
            for (int nt = 0; nt < 8; ++nt) {
                int c = ncol0 + 8 * nt + 2 * tidg;
                float2 brv = *(const float2*)(vecs + 768 + c);
                agg[nt][0] += wf01 * (acc[nt][0] + brv.x);
                agg[nt][1] += wf01 * (acc[nt][1] + brv.y);
                agg[nt][2] += wf01 * (acc[nt][2] + brv.x);
                agg[nt][3] += wf01 * (acc[nt][3] + brv.y);
            }
        }

        // ---- G1: h1 = rbf @ W1 ----
#pragma unroll
        for (int nt = 0; nt < 8; ++nt)
#pragma unroll
            for (int c = 0; c < 4; ++c) acc[nt][c] = 0.0f;
        gemm_frag(acc, rbf_u, S_A, W1u, NB / 8, mrow0, ncol0, gid, tidg);

        // ---- LN1 + gelu -> hbuf (tf32) ----
        {
            float sum0 = 0.f, sq0 = 0.f, sum1 = 0.f, sq1 = 0.f;
#pragma unroll
            for (int nt = 0; nt < 8; ++nt) {
                int c = ncol0 + 8 * nt + 2 * tidg;
                float2 bv = *(const float2*)(vecs + c);
                float v0 = acc[nt][0] + bv.x, v1 = acc[nt][1] + bv.y;
                float v2 = acc[nt][2] + bv.x, v3 = acc[nt][3] + bv.y;
                acc[nt][0] = v0; acc[nt][1] = v1; acc[nt][2] = v2; acc[nt][3] = v3;
                sum0 += v0 + v1; sq0 += v0 * v0 + v1 * v1;
                sum1 += v2 + v3; sq1 += v2 * v2 + v3 * v3;
            }
            sum0 = qred(sum0); sq0 = qred(sq0);
            sum1 = qred(sum1); sq1 = qred(sq1);
            int row0 = mrow0 + gid;
            if (tidg == 0) {
                lnred[row0 * 2 + nwid]       = make_float2(sum0, sq0);
                lnred[(row0 + 8) * 2 + nwid] = make_float2(sum1, sq1);
            }
            __syncthreads();
            float2 p0 = lnred[row0 * 2 + (1 - nwid)];
            float2 p1 = lnred[(row0 + 8) * 2 + (1 - nwid)];
            float mu0 = (sum0 + p0.x) * (1.0f / H1);
            float mu1 = (sum1 + p1.x) * (1.0f / H1);
            float in0 = rsqrtf((sq0 + p0.y) * (1.0f / H1) - mu0 * mu0 + LN_EPS);
            float in1 = rsqrtf((sq1 + p1.y) * (1.0f / H1) - mu1 * mu1 + LN_EPS);
#pragma unroll
            for (int nt = 0; nt < 8; ++nt) {
                int c = ncol0 + 8 * nt + 2 * tidg;
                float2 gv  = *(const float2*)(vecs + 128 + c);
                float2 bev = *(const float2*)(vecs + 256 + c);
                float h0 = gelu_exact((acc[nt][0] - mu0) * in0 * gv.x + bev.x);
                float h1 = gelu_exact((acc[nt][1] - mu0) * in0 * gv.y + bev.y);
                float h2 = gelu_exact((acc[nt][2] - mu1) * in1 * gv.x + bev.x);
                float h3 = gelu_exact((acc[nt][3] - mu1) * in1 * gv.y + bev.y);
                *(uint2*)(hbuf_u + row0 * S_H + c)       = make_uint2(to_tf32(h0), to_tf32(h1));
                *(uint2*)(hbuf_u + (row0 + 8) * S_H + c) = make_uint2(to_tf32(h2), to_tf32(h3));
            }
        }
        __syncthreads();   // hbuf complete before G2 reads

        // ---- G2: h2pre = h @ W2 ----
#pragma unroll
        for (int nt = 0; nt < 8; ++nt)
#pragma unroll
            for (int c = 0; c < 4; ++c) acc[nt][c] = 0.0f;
        gemm_frag(acc, hbuf_u, S_H, W2u, H1 / 8, mrow0, ncol0, gid, tidg);

        // ---- LN2 + gelu; agg += wf * h2 ----
        {
            float sum0 = 0.f, sq0 = 0.f, sum1 = 0.f, sq1 = 0.f;
#pragma unroll
            for (int nt = 0; nt < 8; ++nt) {
                int c = ncol0 + 8 * nt + 2 * tidg;
                float2 bv = *(const float2*)(vecs + 384 + c);
                float v0 = acc[nt][0] + bv.x, v1 = acc[nt][1] + bv.y;
                float v2 = acc[nt][2] + bv.x, v3 = acc[nt][3] + bv.y;
                acc[nt][0] = v0; acc[nt][1] = v1; acc[nt][2] = v2; acc[nt][3] = v3;
                sum0 += v0 + v1; sq0 += v0 * v0 + v1 * v1;
                sum1 += v2 + v3; sq1 += v2 * v2 + v3 * v3;
            }
            sum0 = qred(sum0); sq0 = qred(sq0);
            sum1 = qred(sum1); sq1 = qred(sq1);
            int row0 = mrow0 + gid;
            if (tidg == 0) {
                lnred[row0 * 2 + nwid]       = make_float2(sum0, sq0);
                lnred[(row0 + 8) * 2 + nwid] = make_float2(sum1, sq1);
            }
            __syncthreads();
            float2 p0 = lnred[row0 * 2 + (1 - nwid)];
            float2 p1 = lnred[(row0 + 8) * 2 + (1 - nwid)];
            float mu0 = (sum0 + p0.x) * (1.0f / H2);
            float mu1 = (sum1 + p1.x) * (1.0f / H2);
            float in0 = rsqrtf((sq0 + p0.y) * (1.0f / H2) - mu0 * mu0 + LN_EPS);
            float in1 = rsqrtf((sq1 + p1.y) * (1.0f / H2) - mu1 * mu1 + LN_EPS);
            float wf = w_s[f];
#pragma unroll
            for (int nt = 0; nt < 8; ++nt) {
                int c = ncol0 + 8 * nt + 2 * tidg;
                float2 gv  = *(const float2*)(vecs + 512 + c);
                float2 bev = *(const float2*)(vecs + 640 + c);
                agg[nt][0] += wf * gelu_exact((acc[nt][0] - mu0) * in0 * gv.x + bev.x);
                agg[nt][1] += wf * gelu_exact((acc[nt][1] - mu0) * in0 * gv.y + bev.y);
                agg[nt][2] += wf * gelu_exact((acc[nt][2] - mu1) * in1 * gv.x + bev.x);
                agg[nt][3] += wf * gelu_exact((acc[nt][3] - mu1) * in1 * gv.y + bev.y);
            }
        }
    }

    // ---- head ----
    {
        int row0 = mrow0 + gid;
        float P[9], Q[9];
#pragma unroll
        for (int q = 0; q < 9; ++q) { P[q] = 0.f; Q[q] = 0.f; }
#pragma unroll
        for (int nt = 0; nt < 8; ++nt) {
            int c = ncol0 + 8 * nt + 2 * tidg;
            float bs0 = __ldg(bias + c), bs1 = __ldg(bias + c + 1);
            float a0 = agg[nt][0] + bs0, a1 = agg[nt][1] + bs1;
            float a2 = agg[nt][2] + bs0, a3 = agg[nt][3] + bs1;
#pragma unroll
            for (int j = 0; j < 3; ++j) {
                float wp0 = __ldg(Wpi + c * 3 + j), wp1 = __ldg(Wpi + (c + 1) * 3 + j);
                float wa0 = __ldg(Wa  + c * 3 + j), wa1 = __ldg(Wa  + (c + 1) * 3 + j);
                float wb0 = __ldg(Wb  + c * 3 + j), wb1 = __ldg(Wb  + (c + 1) * 3 + j);
                P[j]     += a0 * wp0 + a1 * wp1;  Q[j]     += a2 * wp0 + a3 * wp1;
                P[3 + j] += a0 * wa0 + a1 * wa1;  Q[3 + j] += a2 * wa0 + a3 * wa1;
                P[6 + j] += a0 * wb0 + a1 * wb1;  Q[6 + j] += a2 * wb0 + a3 * wb1;
            }
        }
#pragma unroll
        for (int q = 0; q < 9; ++q) { P[q] = qred(P[q]); Q[q] = qred(Q[q]); }

        if (nwid == 1 && tidg == 0) {
#pragma unroll
            for (int q = 0; q < 9; ++q) {
                hred[row0 * 9 + q]       = P[q];
                hred[(row0 + 8) * 9 + q] = Q[q];
            }
        }
        __syncthreads();
        if (nwid == 0 && tidg == 0) {
#pragma unroll
            for (int half = 0; half < 2; ++half) {
                int row = row0 + 8 * half;
                float* S = half ? Q : P;
                float s0 = S[0] + hred[row * 9 + 0];
                float s1 = S[1] + hred[row * 9 + 1];
                float s2 = S[2] + hred[row * 9 + 2];
                float A0 = S[3] + hred[row * 9 + 3];
                float A1 = S[4] + hred[row * 9 + 4];
                float A2 = S[5] + hred[row * 9 + 5];
                float C0 = S[6] + hred[row * 9 + 6];
                float C1 = S[7] + hred[row * 9 + 7];
                float C2 = S[8] + hred[row * 9 + 8];
                float l0 = s0 + __ldg(bpi + 0);
                float l1 = s1 + __ldg(bpi + 1);
                float l2 = s2 + __ldg(bpi + 2);
                float m = fmaxf(l0, fmaxf(l1, l2));
                float e0 = expf(l0 - m), e1 = expf(l1 - m), e2 = expf(l2 - m);
                float inv_es = 1.0f / (e0 + e1 + e2);
                float ak0 = clipf(softplus_f(A0 + __ldg(ba + 0)) + 1.01f, 1.01f, 100.0f);
                float ak1 = clipf(softplus_f(A1 + __ldg(ba + 1)) + 1.01f, 1.01f, 100.0f);
                float ak2 = clipf(softplus_f(A2 + __ldg(ba + 2)) + 1.01f, 1.01f, 100.0f);
                float bk0 = clipf(softplus_f(C0 + __ldg(bb + 0)) + 1.01f, 1.01f, 100.0f);
                float bk1 = clipf(softplus_f(C1 + __ldg(bb + 1)) + 1.01f, 1.01f, 100.0f);
                float bk2 = clipf(softplus_f(C2 + __ldg(bb + 2)) + 1.01f, 1.01f, 100.0f);
                float pred = (e0 * inv_es) * (ak0 / (ak0 + bk0))
                           + (e1 * inv_es) * (ak1 / (ak1 + bk1))
                           + (e2 * inv_es) * (ak2 / (ak2 + bk2));
                out[base_row + row] = clipf(pred, 0.001f, 0.999f);
            }
        }
    }
}

extern "C" void kernel_launch(void* const* d_in, const int* in_sizes, int n_in,
                              void* d_out, int out_size) {
    (void)in_sizes; (void)n_in; (void)out_size;
    cudaFuncSetAttribute(nam_kernel,
                         cudaFuncAttributeMaxDynamicSharedMemorySize, SMEM_BYTES);
    const float* x       = (const float*)d_in[0];
    const float* centers = (const float*)d_in[1];
    const float* logw    = (const float*)d_in[2];
    const float* W1      = (const float*)d_in[3];
    const float* b1      = (const float*)d_in[4];
    const float* g1      = (const float*)d_in[5];
    const float* be1     = (const float*)d_in[6];
    const float* W2      = (const float*)d_in[7];
    const float* b2      = (const float*)d_in[8];
    const float* g2      = (const float*)d_in[9];
    const float* be2     = (const float*)d_in[10];
    const float* Wr      = (const float*)d_in[11];
    const float* br      = (const float*)d_in[12];
    const float* att     = (const float*)d_in[13];
    const float* bias    = (const float*)d_in[14];
    const float* Wpi     = (const float*)d_in[15];
    const float* bpi     = (const float*)d_in[16];
    const float* Wa      = (const float*)d_in[17];
    const float* ba      = (const float*)d_in[18];
    const float* Wb      = (const float*)d_in[19];
    const float* bb      = (const float*)d_in[20];
    float* out = (float*)d_out;

    nam_kernel<<<B_TOT / TM, NTHR, SMEM_BYTES>>>(
        x, centers, logw, W1, b1, g1, be1, W2, b2, g2, be2, Wr, br,
        att, bias, Wpi, bpi, Wa, ba, Wb, bb, out);
}

// round 11
// speedup vs baseline: 2.5680x; 1.0376x over previous
#include <cuda_runtime.h>
#include <math.h>

// ---------------------------------------------------------------------------
// NAM-LSS V2 fused kernel, v7: tf32 mma.sync fragment GEMMs, raw-bits
// staging (NO cvt.rna.tf32 — HMMA.tf32 reads the tf32 field of the fp32
// register; truncation). Eliminates ~4096 ALU cvts/thread that dominated
// v6's issue stream (alu was 27.2%).
// Structure unchanged from v6: 128 CTAs x 512 thr, 8m x 2n warp grid,
// per feature: stage -> rbf -> G3(fold) -> G1 -> LN1+gelu -> G2 ->
// LN2+gelu -> agg. Padded smem strides (68/132/136) = conflict-free.
// ---------------------------------------------------------------------------

namespace {
constexpr int B_TOT  = 16384;
constexpr int F      = 64;
constexpr int NB     = 64;
constexpr int H1     = 128;
constexpr int H2     = 128;
constexpr int TM     = 128;
constexpr int NTHR   = 512;    // 16 warps
constexpr float LN_EPS = 1e-5f;

constexpr int S_W = 136;   // weight smem row stride (floats), 136%32==8
constexpr int S_A = 68;    // rbf row stride, 68%32==4
constexpr int S_H = 132;   // hbuf row stride, 132%32==4

constexpr int OFF_W1   = 0;                       // [64][136]
constexpr int OFF_W2   = OFF_W1 + NB * S_W;       // [128][136]
constexpr int OFF_WR   = OFF_W2 + H1 * S_W;       // [64][136]
constexpr int OFF_VEC  = OFF_WR + NB * S_W;       // 7*128
constexpr int OFF_WSM  = OFF_VEC + 7 * 128;
constexpr int OFF_CEN  = OFF_WSM + 64;
constexpr int OFF_IW   = OFF_CEN + 64;
constexpr int OFF_SCR  = OFF_IW + 64;             // rbf [128][68] / hbuf [128][132]
constexpr int SCR_FL   = TM * S_H;
constexpr int OFF_LNR  = OFF_SCR + SCR_FL;        // float2 [128][2]
constexpr int OFF_HR   = OFF_LNR + 512;           // [128][9]
constexpr int SMEM_FLOATS = OFF_HR + 1152;
constexpr int SMEM_BYTES  = SMEM_FLOATS * 4;      // 217,856 B
}

__device__ __forceinline__ void mma8(float* d, const unsigned* a, unsigned b0, unsigned b1) {
    asm("mma.sync.aligned.m16n8k8.row.col.f32.tf32.tf32.f32 "
        "{%0,%1,%2,%3}, {%4,%5,%6,%7}, {%8,%9}, {%0,%1,%2,%3};"
        : "+f"(d[0]), "+f"(d[1]), "+f"(d[2]), "+f"(d[3])
        : "r"(a[0]), "r"(a[1]), "r"(a[2]), "r"(a[3]), "r"(b0), "r"(b1));
}

__device__ __forceinline__ float qred(float v) {   // reduce over 4-lane quad
    v += __shfl_xor_sync(0xffffffffu, v, 1);
    v += __shfl_xor_sync(0xffffffffu, v, 2);
    return v;
}

__device__ __forceinline__ float gelu_exact(float v) {
    return 0.5f * v * (1.0f + erff(v * 0.70710678118654752f));
}

__device__ __forceinline__ float softplus_f(float v) {
    return (v > 20.0f) ? v : log1pf(expf(v));
}

__device__ __forceinline__ float clipf(float v, float lo, float hi) {
    return fminf(fmaxf(v, lo), hi);
}

// acc[8][4] += A[16 x 8K] @ W[8K x 64] (cols ncol0..+63)
__device__ __forceinline__ void gemm_frag(float acc[8][4], const unsigned* Abase, int sa,
                                          const unsigned* Wbase, int ksteps,
                                          int mrow0, int ncol0, int gid, int tidg) {
    for (int s = 0; s < ksteps; ++s) {
        unsigned a[4];
        const unsigned* ap = Abase + (mrow0 + gid) * sa + 8 * s + tidg;
        a[0] = ap[0];
        a[1] = ap[8 * sa];
        a[2] = ap[4];
        a[3] = ap[8 * sa + 4];
        const unsigned* bp  = Wbase + (8 * s + tidg) * S_W + ncol0 + gid;
        const unsigned* bp4 = bp + 4 * S_W;
#pragma unroll
        for (int nt = 0; nt < 8; ++nt)
            mma8(acc[nt], a, bp[8 * nt], bp4[8 * nt]);
    }
}

__global__ void __launch_bounds__(NTHR, 1)
nam_kernel(const float* __restrict__ x,        // [B,F]
           const float* __restrict__ centers,  // [F,NB]
           const float* __restrict__ logw,     // [F,NB]
           const float* __restrict__ W1,       // [F,NB,H1]
           const float* __restrict__ b1,
           const float* __restrict__ g1,
           const float* __restrict__ be1,
           const float* __restrict__ W2,       // [F,H1,H2]
           const float* __restrict__ b2,
           const float* __restrict__ g2,
           const float* __restrict__ be2,
           const float* __restrict__ Wr,       // [F,NB,H2]
           const float* __restrict__ br,
           const float* __restrict__ att,      // [F]
           const float* __restrict__ bias,     // [H2]
           const float* __restrict__ Wpi,      // [H2,3]
           const float* __restrict__ bpi,
           const float* __restrict__ Wa,
           const float* __restrict__ ba,
           const float* __restrict__ Wb,
           const float* __restrict__ bb,
           float* __restrict__ out)            // [B]
{
    extern __shared__ float smem[];
    unsigned* W1u   = (unsigned*)(smem + OFF_W1);
    unsigned* W2u   = (unsigned*)(smem + OFF_W2);
    unsigned* Wru   = (unsigned*)(smem + OFF_WR);
    float*    vecs  = smem + OFF_VEC;
    float*    w_s   = smem + OFF_WSM;
    float*    cen_s = smem + OFF_CEN;
    float*    iw_s  = smem + OFF_IW;
    unsigned* rbf_u  = (unsigned*)(smem + OFF_SCR);  // [128][68]  (phase 1)
    unsigned* hbuf_u = (unsigned*)(smem + OFF_SCR);  // [128][132] (phase 2, aliased)
    float2*   lnred = (float2*)(smem + OFF_LNR);
    float*    hred  = smem + OFF_HR;

    const int tid  = threadIdx.x;
    const int lane = tid & 31;
    const int wid  = tid >> 5;
    const int gid  = lane >> 2;     // 0..7
    const int tidg = lane & 3;      // 0..3
    const int mwid = wid & 7;       // rows 16*mwid..+15
    const int nwid = wid >> 3;      // cols 64*nwid..+63
    const int mrow0 = 16 * mwid;
    const int ncol0 = 64 * nwid;
    const int base_row = blockIdx.x * TM;

    if (tid < F) {
        float m = -1e30f;
        for (int i = 0; i < F; ++i) m = fmaxf(m, att[i]);
        float s = 0.0f;
        for (int i = 0; i < F; ++i) s += expf(att[i] - m);
        w_s[tid] = expf(att[tid] - m) / s;
    }

    float agg[8][4];
#pragma unroll
    for (int nt = 0; nt < 8; ++nt)
#pragma unroll
        for (int c = 0; c < 4; ++c) agg[nt][c] = 0.0f;

    for (int f = 0; f < F; ++f) {
        __syncthreads();

        // ---- stage weights: raw fp32 bits, padded strides, NO cvt ----
        {
            const uint4* s1 = (const uint4*)(W1 + (size_t)f * NB * H1);
            const uint4* s2 = (const uint4*)(W2 + (size_t)f * H1 * H2);
            const uint4* sr = (const uint4*)(Wr + (size_t)f * NB * H2);
#pragma unroll
            for (int i = 0; i < 4; ++i) {
                int v = tid + i * NTHR;
                *(uint4*)(W1u + (v >> 5) * S_W + (v & 31) * 4) = s1[v];
            }
#pragma unroll
            for (int i = 0; i < 8; ++i) {
                int v = tid + i * NTHR;
                *(uint4*)(W2u + (v >> 5) * S_W + (v & 31) * 4) = s2[v];
            }
#pragma unroll
            for (int i = 0; i < 4; ++i) {
                int v = tid + i * NTHR;
                *(uint4*)(Wru + (v >> 5) * S_W + (v & 31) * 4) = sr[v];
            }
        }
        if (tid < 128) {
            vecs[tid]         = b1 [f * H1 + tid];
            vecs[128 + tid]   = g1 [f * H1 + tid];
            vecs[256 + tid]   = be1[f * H1 + tid];
            vecs[384 + tid]   = b2 [f * H2 + tid];
            vecs[512 + tid]   = g2 [f * H2 + tid];
            vecs[640 + tid]   = be2[f * H2 + tid];
            vecs[768 + tid]   = br [f * H2 + tid];
        } else if (tid >= 256 && tid < 320) {
            int t = tid - 256;
            cen_s[t] = centers[f * NB + t];
            float lw = clipf(logw[f * NB + t], -5.0f, 5.0f);
            iw_s[t] = 1.0f / (expf(lw) + 0.1f);
        }
        __syncthreads();

        // ---- RBF (raw fp32 bits; HMMA truncates to tf32) ----
        {
            int n0 = lane * 2;
            float c0 = cen_s[n0],  c1 = cen_s[n0 + 1];
            float i0 = iw_s[n0],   i1 = iw_s[n0 + 1];
#pragma unroll
            for (int k = 0; k < 8; ++k) {
                int row = wid + 16 * k;
                float xv = clipf(__ldg(x + (size_t)(base_row + row) * F + f), -10.0f, 10.0f);
                float d0 = clipf((xv - c0) * i0, -10.0f, 10.0f);
                float d1v = clipf((xv - c1) * i1, -10.0f, 10.0f);
                float2 e;
                e.x = __expf(-0.5f * d0 * d0);
                e.y = __expf(-0.5f * d1v * d1v);
                *(float2*)((float*)rbf_u + row * S_A + n0) = e;
            }
        }
        __syncthreads();

        float acc[8][4];

        // ---- G3: res = rbf @ Wr ; fold into agg ----
#pragma unroll
        for (int nt = 0; nt < 8; ++nt)
#pragma unroll
            for (int c = 0; c < 4; ++c) acc[nt][c] = 0.0f;
        gemm_frag(acc, rbf_u, S_A, Wru, NB / 8, mrow0, ncol0, gid, tidg);
        {
            float wf01 = 0.1f * w_s[f];
#pragma unroll
            for (int nt = 0; nt < 8; ++nt) {
                int c = ncol0 + 8 * nt + 2 * tidg;
                float2 brv = *(const float2*)(vecs + 768 + c);
                agg[nt][0] += wf01 * (acc[nt][0] + brv.x);
                agg[nt][1] += wf01 * (acc[nt][1] + brv.y);
                agg[nt][2] += wf01 * (acc[nt][2] + brv.x);
                agg[nt][3] += wf01 * (acc[nt][3] + brv.y);
            }
        }

        // ---- G1: h1 = rbf @ W1 ----
#pragma unroll
        for (int nt = 0; nt < 8; ++nt)
#pragma unroll
            for (int c = 0; c < 4; ++c) acc[nt][c] = 0.0f;
        gemm_frag(acc, rbf_u, S_A, W1u, NB / 8, mrow0, ncol0, gid, tidg);

        // ---- LN1 + gelu -> hbuf ----
        {
            float sum0 = 0.f, sq0 = 0.f, sum1 = 0.f, sq1 = 0.f;
#pragma unroll
            for (int nt = 0; nt < 8; ++nt) {
                int c = ncol0 + 8 * nt + 2 * tidg;
                float2 bv = *(const float2*)(vecs + c);
                float v0 = acc[nt][0] + bv.x, v1 = acc[nt][1] + bv.y;
                float v2 = acc[nt][2] + bv.x, v3 = acc[nt][3] + bv.y;
                acc[nt][0] = v0; acc[nt][1] = v1; acc[nt][2] = v2; acc[nt][3] = v3;
                sum0 += v0 + v1; sq0 += v0 * v0 + v1 * v1;
                sum1 += v2 + v3; sq1 += v2 * v2 + v3 * v3;
            }
            sum0 = qred(sum0); sq0 = qred(sq0);
            sum1 = qred(sum1); sq1 = qred(sq1);
            int row0 = mrow0 + gid;
            if (tidg == 0) {
                lnred[row0 * 2 + nwid]       = make_float2(sum0, sq0);
                lnred[(row0 + 8) * 2 + nwid] = make_float2(sum1, sq1);
            }
            __syncthreads();
            float2 p0 = lnred[row0 * 2 + (1 - nwid)];
            float2 p1 = lnred[(row0 + 8) * 2 + (1 - nwid)];
            float mu0 = (sum0 + p0.x) * (1.0f / H1);
            float mu1 = (sum1 + p1.x) * (1.0f / H1);
            float in0 = rsqrtf((sq0 + p0.y) * (1.0f / H1) - mu0 * mu0 + LN_EPS);
            float in1 = rsqrtf((sq1 + p1.y) * (1.0f / H1) - mu1 * mu1 + LN_EPS);
#pragma unroll
            for (int nt = 0; nt < 8; ++nt) {
                int c = ncol0 + 8 * nt + 2 * tidg;
                float2 gv  = *(const float2*)(vecs + 128 + c);
                float2 bev = *(const float2*)(vecs + 256 + c);
                float h0 = gelu_exact((acc[nt][0] - mu0) * in0 * gv.x + bev.x);
                float h1 = gelu_exact((acc[nt][1] - mu0) * in0 * gv.y + bev.y);
                float h2 = gelu_exact((acc[nt][2] - mu1) * in1 * gv.x + bev.x);
                float h3 = gelu_exact((acc[nt][3] - mu1) * in1 * gv.y + bev.y);
                *(float2*)((float*)hbuf_u + row0 * S_H + c)       = make_float2(h0, h1);
                *(float2*)((float*)hbuf_u + (row0 + 8) * S_H + c) = make_float2(h2, h3);
            }
        }
        __syncthreads();

        // ---- G2: h2pre = h @ W2 ----
#pragma unroll
        for (int nt = 0; nt < 8; ++nt)
#pragma unroll
            for (int c = 0; c < 4; ++c) acc[nt][c] = 0.0f;
        gemm_frag(acc, hbuf_u, S_H, W2u, H1 / 8, mrow0, ncol0, gid, tidg);

        // ---- LN2 + gelu; agg += wf * h2 ----
        {
            float sum0 = 0.f, sq0 = 0.f, sum1 = 0.f, sq1 = 0.f;
#pragma unroll
            for (int nt = 0; nt < 8; ++nt) {
                int c = ncol0 + 8 * nt + 2 * tidg;
                float2 bv = *(const float2*)(vecs + 384 + c);
                float v0 = acc[nt][0] + bv.x, v1 = acc[nt][1] + bv.y;
                float v2 = acc[nt][2] + bv.x, v3 = acc[nt][3] + bv.y;
                acc[nt][0] = v0; acc[nt][1] = v1; acc[nt][2] = v2; acc[nt][3] = v3;
                sum0 += v0 + v1; sq0 += v0 * v0 + v1 * v1;
                sum1 += v2 + v3; sq1 += v2 * v2 + v3 * v3;
            }
            sum0 = qred(sum0); sq0 = qred(sq0);
            sum1 = qred(sum1); sq1 = qred(sq1);
            int row0 = mrow0 + gid;
            if (tidg == 0) {
                lnred[row0 * 2 + nwid]       = make_float2(sum0, sq0);
                lnred[(row0 + 8) * 2 + nwid] = make_float2(sum1, sq1);
            }
            __syncthreads();
            float2 p0 = lnred[row0 * 2 + (1 - nwid)];
            float2 p1 = lnred[(row0 + 8) * 2 + (1 - nwid)];
            float mu0 = (sum0 + p0.x) * (1.0f / H2);
            float mu1 = (sum1 + p1.x) * (1.0f / H2);
            float in0 = rsqrtf((sq0 + p0.y) * (1.0f / H2) - mu0 * mu0 + LN_EPS);
            float in1 = rsqrtf((sq1 + p1.y) * (1.0f / H2) - mu1 * mu1 + LN_EPS);
            float wf = w_s[f];
#pragma unroll
            for (int nt = 0; nt < 8; ++nt) {
                int c = ncol0 + 8 * nt + 2 * tidg;
                float2 gv  = *(const float2*)(vecs + 512 + c);
                float2 bev = *(const float2*)(vecs + 640 + c);
                agg[nt][0] += wf * gelu_exact((acc[nt][0] - mu0) * in0 * gv.x + bev.x);
                agg[nt][1] += wf * gelu_exact((acc[nt][1] - mu0) * in0 * gv.y + bev.y);
                agg[nt][2] += wf * gelu_exact((acc[nt][2] - mu1) * in1 * gv.x + bev.x);
                agg[nt][3] += wf * gelu_exact((acc[nt][3] - mu1) * in1 * gv.y + bev.y);
            }
        }
    }

    // ---- head ----
    {
        int row0 = mrow0 + gid;
        float P[9], Q[9];
#pragma unroll
        for (int q = 0; q < 9; ++q) { P[q] = 0.f; Q[q] = 0.f; }
#pragma unroll
        for (int nt = 0; nt < 8; ++nt) {
            int c = ncol0 + 8 * nt + 2 * tidg;
            float bs0 = __ldg(bias + c), bs1 = __ldg(bias + c + 1);
            float a0 = agg[nt][0] + bs0, a1 = agg[nt][1] + bs1;
            float a2 = agg[nt][2] + bs0, a3 = agg[nt][3] + bs1;
#pragma unroll
            for (int j = 0; j < 3; ++j) {
                float wp0 = __ldg(Wpi + c * 3 + j), wp1 = __ldg(Wpi + (c + 1) * 3 + j);
                float wa0 = __ldg(Wa  + c * 3 + j), wa1 = __ldg(Wa  + (c + 1) * 3 + j);
                float wb0 = __ldg(Wb  + c * 3 + j), wb1 = __ldg(Wb  + (c + 1) * 3 + j);
                P[j]     += a0 * wp0 + a1 * wp1;  Q[j]     += a2 * wp0 + a3 * wp1;
                P[3 + j] += a0 * wa0 + a1 * wa1;  Q[3 + j] += a2 * wa0 + a3 * wa1;
                P[6 + j] += a0 * wb0 + a1 * wb1;  Q[6 + j] += a2 * wb0 + a3 * wb1;
            }
        }
#pragma unroll
        for (int q = 0; q < 9; ++q) { P[q] = qred(P[q]); Q[q] = qred(Q[q]); }

        if (nwid == 1 && tidg == 0) {
#pragma unroll
            for (int q = 0; q < 9; ++q) {
                hred[row0 * 9 + q]       = P[q];
                hred[(row0 + 8) * 9 + q] = Q[q];
            }
        }
        __syncthreads();
        if (nwid == 0 && tidg == 0) {
#pragma unroll
            for (int half = 0; half < 2; ++half) {
                int row = row0 + 8 * half;
                float* S = half ? Q : P;
                float s0 = S[0] + hred[row * 9 + 0];
                float s1 = S[1] + hred[row * 9 + 1];
                float s2 = S[2] + hred[row * 9 + 2];
                float A0 = S[3] + hred[row * 9 + 3];
                float A1 = S[4] + hred[row * 9 + 4];
                float A2 = S[5] + hred[row * 9 + 5];
                float C0 = S[6] + hred[row * 9 + 6];
                float C1 = S[7] + hred[row * 9 + 7];
                float C2 = S[8] + hred[row * 9 + 8];
                float l0 = s0 + __ldg(bpi + 0);
                float l1 = s1 + __ldg(bpi + 1);
                float l2 = s2 + __ldg(bpi + 2);
                float m = fmaxf(l0, fmaxf(l1, l2));
                float e0 = expf(l0 - m), e1 = expf(l1 - m), e2 = expf(l2 - m);
                float inv_es = 1.0f / (e0 + e1 + e2);
                float ak0 = clipf(softplus_f(A0 + __ldg(ba + 0)) + 1.01f, 1.01f, 100.0f);
                float ak1 = clipf(softplus_f(A1 + __ldg(ba + 1)) + 1.01f, 1.01f, 100.0f);
                float ak2 = clipf(softplus_f(A2 + __ldg(ba + 2)) + 1.01f, 1.01f, 100.0f);
                float bk0 = clipf(softplus_f(C0 + __ldg(bb + 0)) + 1.01f, 1.01f, 100.0f);
                float bk1 = clipf(softplus_f(C1 + __ldg(bb + 1)) + 1.01f, 1.01f, 100.0f);
                float bk2 = clipf(softplus_f(C2 + __ldg(bb + 2)) + 1.01f, 1.01f, 100.0f);
                float pred = (e0 * inv_es) * (ak0 / (ak0 + bk0))
                           + (e1 * inv_es) * (ak1 / (ak1 + bk1))
                           + (e2 * inv_es) * (ak2 / (ak2 + bk2));
                out[base_row + row] = clipf(pred, 0.001f, 0.999f);
            }
        }
    }
}

extern "C" void kernel_launch(void* const* d_in, const int* in_sizes, int n_in,
                              void* d_out, int out_size) {
    (void)in_sizes; (void)n_in; (void)out_size;
    cudaFuncSetAttribute(nam_kernel,
                         cudaFuncAttributeMaxDynamicSharedMemorySize, SMEM_BYTES);
    const float* x       = (const float*)d_in[0];
    const float* centers = (const float*)d_in[1];
    const float* logw    = (const float*)d_in[2];
    const float* W1      = (const float*)d_in[3];
    const float* b1      = (const float*)d_in[4];
    const float* g1      = (const float*)d_in[5];
    const float* be1     = (const float*)d_in[6];
    const float* W2      = (const float*)d_in[7];
    const float* b2      = (const float*)d_in[8];
    const float* g2      = (const float*)d_in[9];
    const float* be2     = (const float*)d_in[10];
    const float* Wr      = (const float*)d_in[11];
    const float* br      = (const float*)d_in[12];
    const float* att     = (const float*)d_in[13];
    const float* bias    = (const float*)d_in[14];
    const float* Wpi     = (const float*)d_in[15];
    const float* bpi     = (const float*)d_in[16];
    const float* Wa      = (const float*)d_in[17];
    const float* ba      = (const float*)d_in[18];
    const float* Wb      = (const float*)d_in[19];
    const float* bb      = (const float*)d_in[20];
    float* out = (float*)d_out;

    nam_kernel<<<B_TOT / TM, NTHR, SMEM_BYTES>>>(
        x, centers, logw, W1, b1, g1, be1, W2, b2, g2, be2, Wr, br,
        att, bias, Wpi, bpi, Wa, ba, Wb, bb, out);
}

// round 12
// speedup vs baseline: 2.5942x; 1.0102x over previous
#include <cuda_runtime.h>
#include <math.h>

// ---------------------------------------------------------------------------
// NAM-LSS V2 fused kernel, v8: tf32 mma.sync + decoupled pipeline.
//  - rbf/hbuf/LN traffic made PAIR-LOCAL (warp pair mwid = 2 warps, 64 thr):
//    4 of 6 per-feature CTA barriers become named 64-thread barriers.
//  - weight staging via cp.async (LDGSTS), issued before rbf and waited
//    after -> L2 latency hidden under rbf exp work; one CTA sync publishes.
//  - centers/inv-widths computed per-warp in registers (no cen_s staging dep).
// Same math as v7 (raw-bits tf32, truncation): rel_err ~5e-6.
// ---------------------------------------------------------------------------

namespace {
constexpr int B_TOT  = 16384;
constexpr int F      = 64;
constexpr int NB     = 64;
constexpr int H1     = 128;
constexpr int H2     = 128;
constexpr int TM     = 128;
constexpr int NTHR   = 512;    // 16 warps: 8 m-pairs x 2 n-warps
constexpr float LN_EPS = 1e-5f;

constexpr int S_W = 136;   // weight smem row stride (floats), 136%32==8
constexpr int S_A = 68;    // rbf row stride, 68%32==4
constexpr int S_H = 132;   // hbuf row stride, 132%32==4

constexpr int OFF_W1   = 0;                       // [64][136]
constexpr int OFF_W2   = OFF_W1 + NB * S_W;       // [128][136]
constexpr int OFF_WR   = OFF_W2 + H1 * S_W;       // [64][136]
constexpr int OFF_VEC  = OFF_WR + NB * S_W;       // 7*128
constexpr int OFF_WSM  = OFF_VEC + 7 * 128;       // 64
constexpr int OFF_SCR  = OFF_WSM + 64;            // rbf [128][68] / hbuf [128][132]
constexpr int SCR_FL   = TM * S_H;
constexpr int OFF_LNR  = OFF_SCR + SCR_FL;        // float2 [128][2]
constexpr int OFF_HR   = OFF_LNR + 512;           // [128][9]
constexpr int SMEM_FLOATS = OFF_HR + 1152;
constexpr int SMEM_BYTES  = SMEM_FLOATS * 4;      // ~217.3 KB
}

__device__ __forceinline__ void mma8(float* d, const unsigned* a, unsigned b0, unsigned b1) {
    asm("mma.sync.aligned.m16n8k8.row.col.f32.tf32.tf32.f32 "
        "{%0,%1,%2,%3}, {%4,%5,%6,%7}, {%8,%9}, {%0,%1,%2,%3};"
        : "+f"(d[0]), "+f"(d[1]), "+f"(d[2]), "+f"(d[3])
        : "r"(a[0]), "r"(a[1]), "r"(a[2]), "r"(a[3]), "r"(b0), "r"(b1));
}

__device__ __forceinline__ void cp16(unsigned dst, const void* src) {
    asm volatile("cp.async.cg.shared.global [%0], [%1], 16;" :: "r"(dst), "l"(src));
}

__device__ __forceinline__ float qred(float v) {   // reduce over 4-lane quad
    v += __shfl_xor_sync(0xffffffffu, v, 1);
    v += __shfl_xor_sync(0xffffffffu, v, 2);
    return v;
}

__device__ __forceinline__ float gelu_exact(float v) {
    return 0.5f * v * (1.0f + erff(v * 0.70710678118654752f));
}

__device__ __forceinline__ float softplus_f(float v) {
    return (v > 20.0f) ? v : log1pf(expf(v));
}

__device__ __forceinline__ float clipf(float v, float lo, float hi) {
    return fminf(fmaxf(v, lo), hi);
}

// acc[8][4] += A[16 x 8K] @ W[8K x 64] (cols ncol0..+63)
__device__ __forceinline__ void gemm_frag(float acc[8][4], const unsigned* Abase, int sa,
                                          const unsigned* Wbase, int ksteps,
                                          int mrow0, int ncol0, int gid, int tidg) {
    for (int s = 0; s < ksteps; ++s) {
        unsigned a[4];
        const unsigned* ap = Abase + (mrow0 + gid) * sa + 8 * s + tidg;
        a[0] = ap[0];
        a[1] = ap[8 * sa];
        a[2] = ap[4];
        a[3] = ap[8 * sa + 4];
        const unsigned* bp  = Wbase + (8 * s + tidg) * S_W + ncol0 + gid;
        const unsigned* bp4 = bp + 4 * S_W;
#pragma unroll
        for (int nt = 0; nt < 8; ++nt)
            mma8(acc[nt], a, bp[8 * nt], bp4[8 * nt]);
    }
}

__global__ void __launch_bounds__(NTHR, 1)
nam_kernel(const float* __restrict__ x,        // [B,F]
           const float* __restrict__ centers,  // [F,NB]
           const float* __restrict__ logw,     // [F,NB]
           const float* __restrict__ W1,       // [F,NB,H1]
           const float* __restrict__ b1,
           const float* __restrict__ g1,
           const float* __restrict__ be1,
           const float* __restrict__ W2,       // [F,H1,H2]
           const float* __restrict__ b2,
           const float* __restrict__ g2,
           const float* __restrict__ be2,
           const float* __restrict__ Wr,       // [F,NB,H2]
           const float* __restrict__ br,
           const float* __restrict__ att,      // [F]
           const float* __restrict__ bias,     // [H2]
           const float* __restrict__ Wpi,      // [H2,3]
           const float* __restrict__ bpi,
           const float* __restrict__ Wa,
           const float* __restrict__ ba,
           const float* __restrict__ Wb,
           const float* __restrict__ bb,
           float* __restrict__ out)            // [B]
{
    extern __shared__ float smem[];
    unsigned* W1u   = (unsigned*)(smem + OFF_W1);
    unsigned* W2u   = (unsigned*)(smem + OFF_W2);
    unsigned* Wru   = (unsigned*)(smem + OFF_WR);
    float*    vecs  = smem + OFF_VEC;
    float*    w_s   = smem + OFF_WSM;
    unsigned* rbf_u  = (unsigned*)(smem + OFF_SCR);  // [128][68]  (phase 1)
    unsigned* hbuf_u = (unsigned*)(smem + OFF_SCR);  // [128][132] (phase 2, aliased)
    float2*   lnred = (float2*)(smem + OFF_LNR);
    float*    hred  = smem + OFF_HR;

    const int tid  = threadIdx.x;
    const int lane = tid & 31;
    const int wid  = tid >> 5;
    const int gid  = lane >> 2;     // 0..7
    const int tidg = lane & 3;      // 0..3
    const int mwid = wid & 7;       // pair id: rows 16*mwid..+15
    const int nwid = wid >> 3;      // cols 64*nwid..+63
    const int mrow0 = 16 * mwid;
    const int ncol0 = 64 * nwid;
    const int base_row = blockIdx.x * TM;
    const int bar_id = mwid + 1;    // named barrier per pair

    // byte addresses of weight smem regions for cp.async
    const unsigned w1_sm = (unsigned)__cvta_generic_to_shared(W1u);
    const unsigned w2_sm = (unsigned)__cvta_generic_to_shared(W2u);
    const unsigned wr_sm = (unsigned)__cvta_generic_to_shared(Wru);

    if (tid < F) {
        float m = -1e30f;
        for (int i = 0; i < F; ++i) m = fmaxf(m, att[i]);
        float s = 0.0f;
        for (int i = 0; i < F; ++i) s += expf(att[i] - m);
        w_s[tid] = expf(att[tid] - m) / s;
    }

    float agg[8][4];
#pragma unroll
    for (int nt = 0; nt < 8; ++nt)
#pragma unroll
        for (int c = 0; c < 4; ++c) agg[nt][c] = 0.0f;

    for (int f = 0; f < F; ++f) {
        __syncthreads();   // all pairs done with prev feature's weights/scratch/lnred

        // ---- issue weight staging (cp.async, 16B granules, padded scatter) ----
        {
            const char* s1 = (const char*)(W1 + (size_t)f * NB * H1);
            const char* s2 = (const char*)(W2 + (size_t)f * H1 * H2);
            const char* sr = (const char*)(Wr + (size_t)f * NB * H2);
#pragma unroll
            for (int i = 0; i < 4; ++i) {
                int v = tid + i * NTHR;
                cp16(w1_sm + ((v >> 5) * S_W + (v & 31) * 4) * 4, s1 + v * 16);
            }
#pragma unroll
            for (int i = 0; i < 8; ++i) {
                int v = tid + i * NTHR;
                cp16(w2_sm + ((v >> 5) * S_W + (v & 31) * 4) * 4, s2 + v * 16);
            }
#pragma unroll
            for (int i = 0; i < 4; ++i) {
                int v = tid + i * NTHR;
                cp16(wr_sm + ((v >> 5) * S_W + (v & 31) * 4) * 4, sr + v * 16);
            }
            asm volatile("cp.async.commit_group;");
        }
        if (tid < 128) {
            vecs[tid]         = b1 [f * H1 + tid];
            vecs[128 + tid]   = g1 [f * H1 + tid];
            vecs[256 + tid]   = be1[f * H1 + tid];
            vecs[384 + tid]   = b2 [f * H2 + tid];
            vecs[512 + tid]   = g2 [f * H2 + tid];
            vecs[640 + tid]   = be2[f * H2 + tid];
            vecs[768 + tid]   = br [f * H2 + tid];
        }

        // ---- RBF (pair-local rows; per-warp center/width in registers) ----
        {
            int n0 = lane * 2;
            float c0 = __ldg(centers + f * NB + n0);
            float c1 = __ldg(centers + f * NB + n0 + 1);
            float i0 = 1.0f / (expf(clipf(__ldg(logw + f * NB + n0),     -5.0f, 5.0f)) + 0.1f);
            float i1 = 1.0f / (expf(clipf(__ldg(logw + f * NB + n0 + 1), -5.0f, 5.0f)) + 0.1f);
            int r0 = mrow0 + 8 * nwid;
#pragma unroll
            for (int rr = 0; rr < 8; ++rr) {
                int row = r0 + rr;
                float xv = clipf(__ldg(x + (size_t)(base_row + row) * F + f), -10.0f, 10.0f);
                float d0 = clipf((xv - c0) * i0, -10.0f, 10.0f);
                float d1v = clipf((xv - c1) * i1, -10.0f, 10.0f);
                float2 e;
                e.x = __expf(-0.5f * d0 * d0);
                e.y = __expf(-0.5f * d1v * d1v);
                *(float2*)((float*)rbf_u + row * S_A + n0) = e;
            }
        }

        // ---- weights + rbf + vecs ready ----
        asm volatile("cp.async.wait_group 0;" ::: "memory");
        __syncthreads();

        float acc[8][4];

        // ---- G3: res = rbf @ Wr ; fold into agg ----
#pragma unroll
        for (int nt = 0; nt < 8; ++nt)
#pragma unroll
            for (int c = 0; c < 4; ++c) acc[nt][c] = 0.0f;
        gemm_frag(acc, rbf_u, S_A, Wru, NB / 8, mrow0, ncol0, gid, tidg);
        {
            float wf01 = 0.1f * w_s[f];
#pragma unroll
            for (int nt = 0; nt < 8; ++nt) {
                int c = ncol0 + 8 * nt + 2 * tidg;
                float2 brv = *(const float2*)(vecs + 768 + c);
                agg[nt][0] += wf01 * (acc[nt][0] + brv.x);
                agg[nt][1] += wf01 * (acc[nt][1] + brv.y);
                agg[nt][2] += wf01 * (acc[nt][2] + brv.x);
                agg[nt][3] += wf01 * (acc[nt][3] + brv.y);
            }
        }

        // ---- G1: h1 = rbf @ W1 ----
#pragma unroll
        for (int nt = 0; nt < 8; ++nt)
#pragma unroll
            for (int c = 0; c < 4; ++c) acc[nt][c] = 0.0f;
        gemm_frag(acc, rbf_u, S_A, W1u, NB / 8, mrow0, ncol0, gid, tidg);

        // ---- LN1 + gelu -> hbuf (pair-scoped) ----
        {
            float sum0 = 0.f, sq0 = 0.f, sum1 = 0.f, sq1 = 0.f;
#pragma unroll
            for (int nt = 0; nt < 8; ++nt) {
                int c = ncol0 + 8 * nt + 2 * tidg;
                float2 bv = *(const float2*)(vecs + c);
                float v0 = acc[nt][0] + bv.x, v1 = acc[nt][1] + bv.y;
                float v2 = acc[nt][2] + bv.x, v3 = acc[nt][3] + bv.y;
                acc[nt][0] = v0; acc[nt][1] = v1; acc[nt][2] = v2; acc[nt][3] = v3;
                sum0 += v0 + v1; sq0 += v0 * v0 + v1 * v1;
                sum1 += v2 + v3; sq1 += v2 * v2 + v3 * v3;
            }
            sum0 = qred(sum0); sq0 = qred(sq0);
            sum1 = qred(sum1); sq1 = qred(sq1);
            int row0 = mrow0 + gid;
            if (tidg == 0) {
                lnred[row0 * 2 + nwid]       = make_float2(sum0, sq0);
                lnred[(row0 + 8) * 2 + nwid] = make_float2(sum1, sq1);
            }
            asm volatile("bar.sync %0, 64;" :: "r"(bar_id) : "memory");
            float2 p0 = lnred[row0 * 2 + (1 - nwid)];
            float2 p1 = lnred[(row0 + 8) * 2 + (1 - nwid)];
            float mu0 = (sum0 + p0.x) * (1.0f / H1);
            float mu1 = (sum1 + p1.x) * (1.0f / H1);
            float in0 = rsqrtf((sq0 + p0.y) * (1.0f / H1) - mu0 * mu0 + LN_EPS);
            float in1 = rsqrtf((sq1 + p1.y) * (1.0f / H1) - mu1 * mu1 + LN_EPS);
#pragma unroll
            for (int nt = 0; nt < 8; ++nt) {
                int c = ncol0 + 8 * nt + 2 * tidg;
                float2 gv  = *(const float2*)(vecs + 128 + c);
                float2 bev = *(const float2*)(vecs + 256 + c);
                float h0 = gelu_exact((acc[nt][0] - mu0) * in0 * gv.x + bev.x);
                float h1 = gelu_exact((acc[nt][1] - mu0) * in0 * gv.y + bev.y);
                float h2 = gelu_exact((acc[nt][2] - mu1) * in1 * gv.x + bev.x);
                float h3 = gelu_exact((acc[nt][3] - mu1) * in1 * gv.y + bev.y);
                *(float2*)((float*)hbuf_u + row0 * S_H + c)       = make_float2(h0, h1);
                *(float2*)((float*)hbuf_u + (row0 + 8) * S_H + c) = make_float2(h2, h3);
            }
        }
        asm volatile("bar.sync %0, 64;" :: "r"(bar_id) : "memory");  // hbuf ready (pair)

        // ---- G2: h2pre = h @ W2 (A rows pair-local) ----
#pragma unroll
        for (int nt = 0; nt < 8; ++nt)
#pragma unroll
            for (int c = 0; c < 4; ++c) acc[nt][c] = 0.0f;
        gemm_frag(acc, hbuf_u, S_H, W2u, H1 / 8, mrow0, ncol0, gid, tidg);

        // ---- LN2 + gelu; agg += wf * h2 (pair-scoped) ----
        {
            float sum0 = 0.f, sq0 = 0.f, sum1 = 0.f, sq1 = 0.f;
#pragma unroll
            for (int nt = 0; nt < 8; ++nt) {
                int c = ncol0 + 8 * nt + 2 * tidg;
                float2 bv = *(const float2*)(vecs + 384 + c);
                float v0 = acc[nt][0] + bv.x, v1 = acc[nt][1] + bv.y;
                float v2 = acc[nt][2] + bv.x, v3 = acc[nt][3] + bv.y;
                acc[nt][0] = v0; acc[nt][1] = v1; acc[nt][2] = v2; acc[nt][3] = v3;
                sum0 += v0 + v1; sq0 += v0 * v0 + v1 * v1;
                sum1 += v2 + v3; sq1 += v2 * v2 + v3 * v3;
            }
            sum0 = qred(sum0); sq0 = qred(sq0);
            sum1 = qred(sum1); sq1 = qred(sq1);
            int row0 = mrow0 + gid;
            if (tidg == 0) {
                lnred[row0 * 2 + nwid]       = make_float2(sum0, sq0);
                lnred[(row0 + 8) * 2 + nwid] = make_float2(sum1, sq1);
            }
            asm volatile("bar.sync %0, 64;" :: "r"(bar_id) : "memory");
            float2 p0 = lnred[row0 * 2 + (1 - nwid)];
            float2 p1 = lnred[(row0 + 8) * 2 + (1 - nwid)];
            float mu0 = (sum0 + p0.x) * (1.0f / H2);
            float mu1 = (sum1 + p1.x) * (1.0f / H2);
            float in0 = rsqrtf((sq0 + p0.y) * (1.0f / H2) - mu0 * mu0 + LN_EPS);
            float in1 = rsqrtf((sq1 + p1.y) * (1.0f / H2) - mu1 * mu1 + LN_EPS);
            float wf = w_s[f];
#pragma unroll
            for (int nt = 0; nt < 8; ++nt) {
                int c = ncol0 + 8 * nt + 2 * tidg;
                float2 gv  = *(const float2*)(vecs + 512 + c);
                float2 bev = *(const float2*)(vecs + 640 + c);
                agg[nt][0] += wf * gelu_exact((acc[nt][0] - mu0) * in0 * gv.x + bev.x);
                agg[nt][1] += wf * gelu_exact((acc[nt][1] - mu0) * in0 * gv.y + bev.y);
                agg[nt][2] += wf * gelu_exact((acc[nt][2] - mu1) * in1 * gv.x + bev.x);
                agg[nt][3] += wf * gelu_exact((acc[nt][3] - mu1) * in1 * gv.y + bev.y);
            }
        }
    }

    // ---- head ----
    {
        int row0 = mrow0 + gid;
        float P[9], Q[9];
#pragma unroll
        for (int q = 0; q < 9; ++q) { P[q] = 0.f; Q[q] = 0.f; }
#pragma unroll
        for (int nt = 0; nt < 8; ++nt) {
            int c = ncol0 + 8 * nt + 2 * tidg;
            float bs0 = __ldg(bias + c), bs1 = __ldg(bias + c + 1);
            float a0 = agg[nt][0] + bs0, a1 = agg[nt][1] + bs1;
            float a2 = agg[nt][2] + bs0, a3 = agg[nt][3] + bs1;
#pragma unroll
            for (int j = 0; j < 3; ++j) {
                float wp0 = __ldg(Wpi + c * 3 + j), wp1 = __ldg(Wpi + (c + 1) * 3 + j);
                float wa0 = __ldg(Wa  + c * 3 + j), wa1 = __ldg(Wa  + (c + 1) * 3 + j);
                float wb0 = __ldg(Wb  + c * 3 + j), wb1 = __ldg(Wb  + (c + 1) * 3 + j);
                P[j]     += a0 * wp0 + a1 * wp1;  Q[j]     += a2 * wp0 + a3 * wp1;
                P[3 + j] += a0 * wa0 + a1 * wa1;  Q[3 + j] += a2 * wa0 + a3 * wa1;
                P[6 + j] += a0 * wb0 + a1 * wb1;  Q[6 + j] += a2 * wb0 + a3 * wb1;
            }
        }
#pragma unroll
        for (int q = 0; q < 9; ++q) { P[q] = qred(P[q]); Q[q] = qred(Q[q]); }

        if (nwid == 1 && tidg == 0) {
#pragma unroll
            for (int q = 0; q < 9; ++q) {
                hred[row0 * 9 + q]       = P[q];
                hred[(row0 + 8) * 9 + q] = Q[q];
            }
        }
        asm volatile("bar.sync %0, 64;" :: "r"(bar_id) : "memory");
        if (nwid == 0 && tidg == 0) {
#pragma unroll
            for (int half = 0; half < 2; ++half) {
                int row = row0 + 8 * half;
                float* S = half ? Q : P;
                float s0 = S[0] + hred[row * 9 + 0];
                float s1 = S[1] + hred[row * 9 + 1];
                float s2 = S[2] + hred[row * 9 + 2];
                float A0 = S[3] + hred[row * 9 + 3];
                float A1 = S[4] + hred[row * 9 + 4];
                float A2 = S[5] + hred[row * 9 + 5];
                float C0 = S[6] + hred[row * 9 + 6];
                float C1 = S[7] + hred[row * 9 + 7];
                float C2 = S[8] + hred[row * 9 + 8];
                float l0 = s0 + __ldg(bpi + 0);
                float l1 = s1 + __ldg(bpi + 1);
                float l2 = s2 + __ldg(bpi + 2);
                float m = fmaxf(l0, fmaxf(l1, l2));
                float e0 = expf(l0 - m), e1 = expf(l1 - m), e2 = expf(l2 - m);
                float inv_es = 1.0f / (e0 + e1 + e2);
                float ak0 = clipf(softplus_f(A0 + __ldg(ba + 0)) + 1.01f, 1.01f, 100.0f);
                float ak1 = clipf(softplus_f(A1 + __ldg(ba + 1)) + 1.01f, 1.01f, 100.0f);
                float ak2 = clipf(softplus_f(A2 + __ldg(ba + 2)) + 1.01f, 1.01f, 100.0f);
                float bk0 = clipf(softplus_f(C0 + __ldg(bb + 0)) + 1.01f, 1.01f, 100.0f);
                float bk1 = clipf(softplus_f(C1 + __ldg(bb + 1)) + 1.01f, 1.01f, 100.0f);
                float bk2 = clipf(softplus_f(C2 + __ldg(bb + 2)) + 1.01f, 1.01f, 100.0f);
                float pred = (e0 * inv_es) * (ak0 / (ak0 + bk0))
                           + (e1 * inv_es) * (ak1 / (ak1 + bk1))
                           + (e2 * inv_es) * (ak2 / (ak2 + bk2));
                out[base_row + row] = clipf(pred, 0.001f, 0.999f);
            }
        }
    }
}

extern "C" void kernel_launch(void* const* d_in, const int* in_sizes, int n_in,
                              void* d_out, int out_size) {
    (void)in_sizes; (void)n_in; (void)out_size;
    cudaFuncSetAttribute(nam_kernel,
                         cudaFuncAttributeMaxDynamicSharedMemorySize, SMEM_BYTES);
    const float* x       = (const float*)d_in[0];
    const float* centers = (const float*)d_in[1];
    const float* logw    = (const float*)d_in[2];
    const float* W1      = (const float*)d_in[3];
    const float* b1      = (const float*)d_in[4];
    const float* g1      = (const float*)d_in[5];
    const float* be1     = (const float*)d_in[6];
    const float* W2      = (const float*)d_in[7];
    const float* b2      = (const float*)d_in[8];
    const float* g2      = (const float*)d_in[9];
    const float* be2     = (const float*)d_in[10];
    const float* Wr      = (const float*)d_in[11];
    const float* br      = (const float*)d_in[12];
    const float* att     = (const float*)d_in[13];
    const float* bias    = (const float*)d_in[14];
    const float* Wpi     = (const float*)d_in[15];
    const float* bpi     = (const float*)d_in[16];
    const float* Wa      = (const float*)d_in[17];
    const float* ba      = (const float*)d_in[18];
    const float* Wb      = (const float*)d_in[19];
    const float* bb      = (const float*)d_in[20];
    float* out = (float*)d_out;

    nam_kernel<<<B_TOT / TM, NTHR, SMEM_BYTES>>>(
        x, centers, logw, W1, b1, g1, be1, W2, b2, g2, be2, Wr, br,
        att, bias, Wpi, bpi, Wa, ba, Wb, bb, out);
}

// round 13
// speedup vs baseline: 3.1785x; 1.2252x over previous
#include <cuda_runtime.h>
#include <math.h>

// ---------------------------------------------------------------------------
// NAM-LSS V2 fused kernel, v9: v8 + tanh.approx gelu in the main loop.
// The erff-based exact gelu (64 calls/thread/feature, ~20 instr each) was
// ~35% of the issue stream; tanh.approx.f32 (single MUFU) cuts it to ~6.
// |gelu_tanh - gelu_erf| <= ~3e-4 -> rel_err ~1e-4, inside the 1e-3 gate.
// Head epilogue keeps exact math. Everything else identical to v8.
// ---------------------------------------------------------------------------

namespace {
constexpr int B_TOT  = 16384;
constexpr int F      = 64;
constexpr int NB     = 64;
constexpr int H1     = 128;
constexpr int H2     = 128;
constexpr int TM     = 128;
constexpr int NTHR   = 512;    // 16 warps: 8 m-pairs x 2 n-warps
constexpr float LN_EPS = 1e-5f;

constexpr int S_W = 136;   // weight smem row stride (floats), 136%32==8
constexpr int S_A = 68;    // rbf row stride, 68%32==4
constexpr int S_H = 132;   // hbuf row stride, 132%32==4

constexpr int OFF_W1   = 0;                       // [64][136]
constexpr int OFF_W2   = OFF_W1 + NB * S_W;       // [128][136]
constexpr int OFF_WR   = OFF_W2 + H1 * S_W;       // [64][136]
constexpr int OFF_VEC  = OFF_WR + NB * S_W;       // 7*128
constexpr int OFF_WSM  = OFF_VEC + 7 * 128;       // 64
constexpr int OFF_SCR  = OFF_WSM + 64;            // rbf [128][68] / hbuf [128][132]
constexpr int SCR_FL   = TM * S_H;
constexpr int OFF_LNR  = OFF_SCR + SCR_FL;        // float2 [128][2]
constexpr int OFF_HR   = OFF_LNR + 512;           // [128][9]
constexpr int SMEM_FLOATS = OFF_HR + 1152;
constexpr int SMEM_BYTES  = SMEM_FLOATS * 4;      // ~217.3 KB
}

__device__ __forceinline__ void mma8(float* d, const unsigned* a, unsigned b0, unsigned b1) {
    asm("mma.sync.aligned.m16n8k8.row.col.f32.tf32.tf32.f32 "
        "{%0,%1,%2,%3}, {%4,%5,%6,%7}, {%8,%9}, {%0,%1,%2,%3};"
        : "+f"(d[0]), "+f"(d[1]), "+f"(d[2]), "+f"(d[3])
        : "r"(a[0]), "r"(a[1]), "r"(a[2]), "r"(a[3]), "r"(b0), "r"(b1));
}

__device__ __forceinline__ void cp16(unsigned dst, const void* src) {
    asm volatile("cp.async.cg.shared.global [%0], [%1], 16;" :: "r"(dst), "l"(src));
}

__device__ __forceinline__ float qred(float v) {   // reduce over 4-lane quad
    v += __shfl_xor_sync(0xffffffffu, v, 1);
    v += __shfl_xor_sync(0xffffffffu, v, 2);
    return v;
}

// fast gelu: tanh form with HW tanh.approx (single MUFU op)
__device__ __forceinline__ float gelu_fast(float v) {
    float z = 0.7978845608028654f * fmaf(0.044715f * v, v * v, v);
    float t;
    asm("tanh.approx.f32 %0, %1;" : "=f"(t) : "f"(z));
    return 0.5f * v * (1.0f + t);
}

__device__ __forceinline__ float softplus_f(float v) {
    return (v > 20.0f) ? v : log1pf(expf(v));
}

__device__ __forceinline__ float clipf(float v, float lo, float hi) {
    return fminf(fmaxf(v, lo), hi);
}

// acc[8][4] += A[16 x 8K] @ W[8K x 64] (cols ncol0..+63)
__device__ __forceinline__ void gemm_frag(float acc[8][4], const unsigned* Abase, int sa,
                                          const unsigned* Wbase, int ksteps,
                                          int mrow0, int ncol0, int gid, int tidg) {
    for (int s = 0; s < ksteps; ++s) {
        unsigned a[4];
        const unsigned* ap = Abase + (mrow0 + gid) * sa + 8 * s + tidg;
        a[0] = ap[0];
        a[1] = ap[8 * sa];
        a[2] = ap[4];
        a[3] = ap[8 * sa + 4];
        const unsigned* bp  = Wbase + (8 * s + tidg) * S_W + ncol0 + gid;
        const unsigned* bp4 = bp + 4 * S_W;
#pragma unroll
        for (int nt = 0; nt < 8; ++nt)
            mma8(acc[nt], a, bp[8 * nt], bp4[8 * nt]);
    }
}

__global__ void __launch_bounds__(NTHR, 1)
nam_kernel(const float* __restrict__ x,        // [B,F]
           const float* __restrict__ centers,  // [F,NB]
           const float* __restrict__ logw,     // [F,NB]
           const float* __restrict__ W1,       // [F,NB,H1]
           const float* __restrict__ b1,
           const float* __restrict__ g1,
           const float* __restrict__ be1,
           const float* __restrict__ W2,       // [F,H1,H2]
           const float* __restrict__ b2,
           const float* __restrict__ g2,
           const float* __restrict__ be2,
           const float* __restrict__ Wr,       // [F,NB,H2]
           const float* __restrict__ br,
           const float* __restrict__ att,      // [F]
           const float* __restrict__ bias,     // [H2]
           const float* __restrict__ Wpi,      // [H2,3]
           const float* __restrict__ bpi,
           const float* __restrict__ Wa,
           const float* __restrict__ ba,
           const float* __restrict__ Wb,
           const float* __restrict__ bb,
           float* __restrict__ out)            // [B]
{
    extern __shared__ float smem[];
    unsigned* W1u   = (unsigned*)(smem + OFF_W1);
    unsigned* W2u   = (unsigned*)(smem + OFF_W2);
    unsigned* Wru   = (unsigned*)(smem + OFF_WR);
    float*    vecs  = smem + OFF_VEC;
    float*    w_s   = smem + OFF_WSM;
    unsigned* rbf_u  = (unsigned*)(smem + OFF_SCR);  // [128][68]  (phase 1)
    unsigned* hbuf_u = (unsigned*)(smem + OFF_SCR);  // [128][132] (phase 2, aliased)
    float2*   lnred = (float2*)(smem + OFF_LNR);
    float*    hred  = smem + OFF_HR;

    const int tid  = threadIdx.x;
    const int lane = tid & 31;
    const int wid  = tid >> 5;
    const int gid  = lane >> 2;     // 0..7
    const int tidg = lane & 3;      // 0..3
    const int mwid = wid & 7;       // pair id: rows 16*mwid..+15
    const int nwid = wid >> 3;      // cols 64*nwid..+63
    const int mrow0 = 16 * mwid;
    const int ncol0 = 64 * nwid;
    const int base_row = blockIdx.x * TM;
    const int bar_id = mwid + 1;    // named barrier per pair

    const unsigned w1_sm = (unsigned)__cvta_generic_to_shared(W1u);
    const unsigned w2_sm = (unsigned)__cvta_generic_to_shared(W2u);
    const unsigned wr_sm = (unsigned)__cvta_generic_to_shared(Wru);

    if (tid < F) {
        float m = -1e30f;
        for (int i = 0; i < F; ++i) m = fmaxf(m, att[i]);
        float s = 0.0f;
        for (int i = 0; i < F; ++i) s += expf(att[i] - m);
        w_s[tid] = expf(att[tid] - m) / s;
    }

    float agg[8][4];
#pragma unroll
    for (int nt = 0; nt < 8; ++nt)
#pragma unroll
        for (int c = 0; c < 4; ++c) agg[nt][c] = 0.0f;

    for (int f = 0; f < F; ++f) {
        __syncthreads();

        // ---- issue weight staging (cp.async) ----
        {
            const char* s1 = (const char*)(W1 + (size_t)f * NB * H1);
            const char* s2 = (const char*)(W2 + (size_t)f * H1 * H2);
            const char* sr = (const char*)(Wr + (size_t)f * NB * H2);
#pragma unroll
            for (int i = 0; i < 4; ++i) {
                int v = tid + i * NTHR;
                cp16(w1_sm + ((v >> 5) * S_W + (v & 31) * 4) * 4, s1 + v * 16);
            }
#pragma unroll
            for (int i = 0; i < 8; ++i) {
                int v = tid + i * NTHR;
                cp16(w2_sm + ((v >> 5) * S_W + (v & 31) * 4) * 4, s2 + v * 16);
            }
#pragma unroll
            for (int i = 0; i < 4; ++i) {
                int v = tid + i * NTHR;
                cp16(wr_sm + ((v >> 5) * S_W + (v & 31) * 4) * 4, sr + v * 16);
            }
            asm volatile("cp.async.commit_group;");
        }
        if (tid < 128) {
            vecs[tid]         = b1 [f * H1 + tid];
            vecs[128 + tid]   = g1 [f * H1 + tid];
            vecs[256 + tid]   = be1[f * H1 + tid];
            vecs[384 + tid]   = b2 [f * H2 + tid];
            vecs[512 + tid]   = g2 [f * H2 + tid];
            vecs[640 + tid]   = be2[f * H2 + tid];
            vecs[768 + tid]   = br [f * H2 + tid];
        }

        // ---- RBF (pair-local rows) ----
        {
            int n0 = lane * 2;
            float c0 = __ldg(centers + f * NB + n0);
            float c1 = __ldg(centers + f * NB + n0 + 1);
            float i0 = 1.0f / (expf(clipf(__ldg(logw + f * NB + n0),     -5.0f, 5.0f)) + 0.1f);
            float i1 = 1.0f / (expf(clipf(__ldg(logw + f * NB + n0 + 1), -5.0f, 5.0f)) + 0.1f);
            int r0 = mrow0 + 8 * nwid;
#pragma unroll
            for (int rr = 0; rr < 8; ++rr) {
                int row = r0 + rr;
                float xv = clipf(__ldg(x + (size_t)(base_row + row) * F + f), -10.0f, 10.0f);
                float d0 = clipf((xv - c0) * i0, -10.0f, 10.0f);
                float d1v = clipf((xv - c1) * i1, -10.0f, 10.0f);
                float2 e;
                e.x = __expf(-0.5f * d0 * d0);
                e.y = __expf(-0.5f * d1v * d1v);
                *(float2*)((float*)rbf_u + row * S_A + n0) = e;
            }
        }

        asm volatile("cp.async.wait_group 0;" ::: "memory");
        __syncthreads();

        float acc[8][4];

        // ---- G3: res = rbf @ Wr ; fold into agg ----
#pragma unroll
        for (int nt = 0; nt < 8; ++nt)
#pragma unroll
            for (int c = 0; c < 4; ++c) acc[nt][c] = 0.0f;
        gemm_frag(acc, rbf_u, S_A, Wru, NB / 8, mrow0, ncol0, gid, tidg);
        {
            float wf01 = 0.1f * w_s[f];
#pragma unroll
            for (int nt = 0; nt < 8; ++nt) {
                int c = ncol0 + 8 * nt + 2 * tidg;
                float2 brv = *(const float2*)(vecs + 768 + c);
                agg[nt][0] += wf01 * (acc[nt][0] + brv.x);
                agg[nt][1] += wf01 * (acc[nt][1] + brv.y);
                agg[nt][2] += wf01 * (acc[nt][2] + brv.x);
                agg[nt][3] += wf01 * (acc[nt][3] + brv.y);
            }
        }

        // ---- G1: h1 = rbf @ W1 ----
#pragma unroll
        for (int nt = 0; nt < 8; ++nt)
#pragma unroll
            for (int c = 0; c < 4; ++c) acc[nt][c] = 0.0f;
        gemm_frag(acc, rbf_u, S_A, W1u, NB / 8, mrow0, ncol0, gid, tidg);

        // ---- LN1 + gelu -> hbuf (pair-scoped) ----
        {
            float sum0 = 0.f, sq0 = 0.f, sum1 = 0.f, sq1 = 0.f;
#pragma unroll
            for (int nt = 0; nt < 8; ++nt) {
                int c = ncol0 + 8 * nt + 2 * tidg;
                float2 bv = *(const float2*)(vecs + c);
                float v0 = acc[nt][0] + bv.x, v1 = acc[nt][1] + bv.y;
                float v2 = acc[nt][2] + bv.x, v3 = acc[nt][3] + bv.y;
                acc[nt][0] = v0; acc[nt][1] = v1; acc[nt][2] = v2; acc[nt][3] = v3;
                sum0 += v0 + v1; sq0 += v0 * v0 + v1 * v1;
                sum1 += v2 + v3; sq1 += v2 * v2 + v3 * v3;
            }
            sum0 = qred(sum0); sq0 = qred(sq0);
            sum1 = qred(sum1); sq1 = qred(sq1);
            int row0 = mrow0 + gid;
            if (tidg == 0) {
                lnred[row0 * 2 + nwid]       = make_float2(sum0, sq0);
                lnred[(row0 + 8) * 2 + nwid] = make_float2(sum1, sq1);
            }
            asm volatile("bar.sync %0, 64;" :: "r"(bar_id) : "memory");
            float2 p0 = lnred[row0 * 2 + (1 - nwid)];
            float2 p1 = lnred[(row0 + 8) * 2 + (1 - nwid)];
            float mu0 = (sum0 + p0.x) * (1.0f / H1);
            float mu1 = (sum1 + p1.x) * (1.0f / H1);
            float in0 = rsqrtf((sq0 + p0.y) * (1.0f / H1) - mu0 * mu0 + LN_EPS);
            float in1 = rsqrtf((sq1 + p1.y) * (1.0f / H1) - mu1 * mu1 + LN_EPS);
#pragma unroll
            for (int nt = 0; nt < 8; ++nt) {
                int c = ncol0 + 8 * nt + 2 * tidg;
                float2 gv  = *(const float2*)(vecs + 128 + c);
                float2 bev = *(const float2*)(vecs + 256 + c);
                float h0 = gelu_fast((acc[nt][0] - mu0) * in0 * gv.x + bev.x);
                float h1 = gelu_fast((acc[nt][1] - mu0) * in0 * gv.y + bev.y);
                float h2 = gelu_fast((acc[nt][2] - mu1) * in1 * gv.x + bev.x);
                float h3 = gelu_fast((acc[nt][3] - mu1) * in1 * gv.y + bev.y);
                *(float2*)((float*)hbuf_u + row0 * S_H + c)       = make_float2(h0, h1);
                *(float2*)((float*)hbuf_u + (row0 + 8) * S_H + c) = make_float2(h2, h3);
            }
        }
        asm volatile("bar.sync %0, 64;" :: "r"(bar_id) : "memory");  // hbuf ready (pair)

        // ---- G2: h2pre = h @ W2 ----
#pragma unroll
        for (int nt = 0; nt < 8; ++nt)
#pragma unroll
            for (int c = 0; c < 4; ++c) acc[nt][c] = 0.0f;
        gemm_frag(acc, hbuf_u, S_H, W2u, H1 / 8, mrow0, ncol0, gid, tidg);

        // ---- LN2 + gelu; agg += wf * h2 (pair-scoped) ----
        {
            float sum0 = 0.f, sq0 = 0.f, sum1 = 0.f, sq1 = 0.f;
#pragma unroll
            for (int nt = 0; nt < 8; ++nt) {
                int c = ncol0 + 8 * nt + 2 * tidg;
                float2 bv = *(const float2*)(vecs + 384 + c);
                float v0 = acc[nt][0] + bv.x, v1 = acc[nt][1] + bv.y;
                float v2 = acc[nt][2] + bv.x, v3 = acc[nt][3] + bv.y;
                acc[nt][0] = v0; acc[nt][1] = v1; acc[nt][2] = v2; acc[nt][3] = v3;
                sum0 += v0 + v1; sq0 += v0 * v0 + v1 * v1;
                sum1 += v2 + v3; sq1 += v2 * v2 + v3 * v3;
            }
            sum0 = qred(sum0); sq0 = qred(sq0);
            sum1 = qred(sum1); sq1 = qred(sq1);
            int row0 = mrow0 + gid;
            if (tidg == 0) {
                lnred[row0 * 2 + nwid]       = make_float2(sum0, sq0);
                lnred[(row0 + 8) * 2 + nwid] = make_float2(sum1, sq1);
            }
            asm volatile("bar.sync %0, 64;" :: "r"(bar_id) : "memory");
            float2 p0 = lnred[row0 * 2 + (1 - nwid)];
            float2 p1 = lnred[(row0 + 8) * 2 + (1 - nwid)];
            float mu0 = (sum0 + p0.x) * (1.0f / H2);
            float mu1 = (sum1 + p1.x) * (1.0f / H2);
            float in0 = rsqrtf((sq0 + p0.y) * (1.0f / H2) - mu0 * mu0 + LN_EPS);
            float in1 = rsqrtf((sq1 + p1.y) * (1.0f / H2) - mu1 * mu1 + LN_EPS);
            float wf = w_s[f];
#pragma unroll
            for (int nt = 0; nt < 8; ++nt) {
                int c = ncol0 + 8 * nt + 2 * tidg;
                float2 gv  = *(const float2*)(vecs + 512 + c);
                float2 bev = *(const float2*)(vecs + 640 + c);
                agg[nt][0] += wf * gelu_fast((acc[nt][0] - mu0) * in0 * gv.x + bev.x);
                agg[nt][1] += wf * gelu_fast((acc[nt][1] - mu0) * in0 * gv.y + bev.y);
                agg[nt][2] += wf * gelu_fast((acc[nt][2] - mu1) * in1 * gv.x + bev.x);
                agg[nt][3] += wf * gelu_fast((acc[nt][3] - mu1) * in1 * gv.y + bev.y);
            }
        }
    }

    // ---- head (exact math) ----
    {
        int row0 = mrow0 + gid;
        float P[9], Q[9];
#pragma unroll
        for (int q = 0; q < 9; ++q) { P[q] = 0.f; Q[q] = 0.f; }
#pragma unroll
        for (int nt = 0; nt < 8; ++nt) {
            int c = ncol0 + 8 * nt + 2 * tidg;
            float bs0 = __ldg(bias + c), bs1 = __ldg(bias + c + 1);
            float a0 = agg[nt][0] + bs0, a1 = agg[nt][1] + bs1;
            float a2 = agg[nt][2] + bs0, a3 = agg[nt][3] + bs1;
#pragma unroll
            for (int j = 0; j < 3; ++j) {
                float wp0 = __ldg(Wpi + c * 3 + j), wp1 = __ldg(Wpi + (c + 1) * 3 + j);
                float wa0 = __ldg(Wa  + c * 3 + j), wa1 = __ldg(Wa  + (c + 1) * 3 + j);
                float wb0 = __ldg(Wb  + c * 3 + j), wb1 = __ldg(Wb  + (c + 1) * 3 + j);
                P[j]     += a0 * wp0 + a1 * wp1;  Q[j]     += a2 * wp0 + a3 * wp1;
                P[3 + j] += a0 * wa0 + a1 * wa1;  Q[3 + j] += a2 * wa0 + a3 * wa1;
                P[6 + j] += a0 * wb0 + a1 * wb1;  Q[6 + j] += a2 * wb0 + a3 * wb1;
            }
        }
#pragma unroll
        for (int q = 0; q < 9; ++q) { P[q] = qred(P[q]); Q[q] = qred(Q[q]); }

        if (nwid == 1 && tidg == 0) {
#pragma unroll
            for (int q = 0; q < 9; ++q) {
                hred[row0 * 9 + q]       = P[q];
                hred[(row0 + 8) * 9 + q] = Q[q];
            }
        }
        asm volatile("bar.sync %0, 64;" :: "r"(bar_id) : "memory");
        if (nwid == 0 && tidg == 0) {
#pragma unroll
            for (int half = 0; half < 2; ++half) {
                int row = row0 + 8 * half;
                float* S = half ? Q : P;
                float s0 = S[0] + hred[row * 9 + 0];
                float s1 = S[1] + hred[row * 9 + 1];
                float s2 = S[2] + hred[row * 9 + 2];
                float A0 = S[3] + hred[row * 9 + 3];
                float A1 = S[4] + hred[row * 9 + 4];
                float A2 = S[5] + hred[row * 9 + 5];
                float C0 = S[6] + hred[row * 9 + 6];
                float C1 = S[7] + hred[row * 9 + 7];
                float C2 = S[8] + hred[row * 9 + 8];
                float l0 = s0 + __ldg(bpi + 0);
                float l1 = s1 + __ldg(bpi + 1);
                float l2 = s2 + __ldg(bpi + 2);
                float m = fmaxf(l0, fmaxf(l1, l2));
                float e0 = expf(l0 - m), e1 = expf(l1 - m), e2 = expf(l2 - m);
                float inv_es = 1.0f / (e0 + e1 + e2);
                float ak0 = clipf(softplus_f(A0 + __ldg(ba + 0)) + 1.01f, 1.01f, 100.0f);
                float ak1 = clipf(softplus_f(A1 + __ldg(ba + 1)) + 1.01f, 1.01f, 100.0f);
                float ak2 = clipf(softplus_f(A2 + __ldg(ba + 2)) + 1.01f, 1.01f, 100.0f);
                float bk0 = clipf(softplus_f(C0 + __ldg(bb + 0)) + 1.01f, 1.01f, 100.0f);
                float bk1 = clipf(softplus_f(C1 + __ldg(bb + 1)) + 1.01f, 1.01f, 100.0f);
                float bk2 = clipf(softplus_f(C2 + __ldg(bb + 2)) + 1.01f, 1.01f, 100.0f);
                float pred = (e0 * inv_es) * (ak0 / (ak0 + bk0))
                           + (e1 * inv_es) * (ak1 / (ak1 + bk1))
                           + (e2 * inv_es) * (ak2 / (ak2 + bk2));
                out[base_row + row] = clipf(pred, 0.001f, 0.999f);
            }
        }
    }
}

extern "C" void kernel_launch(void* const* d_in, const int* in_sizes, int n_in,
                              void* d_out, int out_size) {
    (void)in_sizes; (void)n_in; (void)out_size;
    cudaFuncSetAttribute(nam_kernel,
                         cudaFuncAttributeMaxDynamicSharedMemorySize, SMEM_BYTES);
    const float* x       = (const float*)d_in[0];
    const float* centers = (const float*)d_in[1];
    const float* logw    = (const float*)d_in[2];
    const float* W1      = (const float*)d_in[3];
    const float* b1      = (const float*)d_in[4];
    const float* g1      = (const float*)d_in[5];
    const float* be1     = (const float*)d_in[6];
    const float* W2      = (const float*)d_in[7];
    const float* b2      = (const float*)d_in[8];
    const float* g2      = (const float*)d_in[9];
    const float* be2     = (const float*)d_in[10];
    const float* Wr      = (const float*)d_in[11];
    const float* br      = (const float*)d_in[12];
    const float* att     = (const float*)d_in[13];
    const float* bias    = (const float*)d_in[14];
    const float* Wpi     = (const float*)d_in[15];
    const float* bpi     = (const float*)d_in[16];
    const float* Wa      = (const float*)d_in[17];
    const float* ba      = (const float*)d_in[18];
    const float* Wb      = (const float*)d_in[19];
    const float* bb      = (const float*)d_in[20];
    float* out = (float*)d_out;

    nam_kernel<<<B_TOT / TM, NTHR, SMEM_BYTES>>>(
        x, centers, logw, W1, b1, g1, be1, W2, b2, g2, be2, Wr, br,
        att, bias, Wpi, bpi, Wa, ba, Wb, bb, out);
}

// round 14
// speedup vs baseline: 4.4784x; 1.4090x over previous
#include <cuda_runtime.h>
#include <cuda_bf16.h>
#include <math.h>

// ---------------------------------------------------------------------------
// NAM-LSS V2 fused kernel, v10: bf16 mma.sync m16n8k16 + prep-transpose.
//  - Prep kernel (per launch, ~3us) transposes W1/W2/Wr to bf16 [f][n][k]
//    in __device__ globals -> hot loop stages half the bytes, no cvt, and
//    B fragments are plain 4B LDS (k-pairs adjacent).
//  - k16 steps halve mma count and fragment-LDS count vs tf32 k8.
//  - A-side scratch (rbf/hbuf) bf16-packed; all smem row strides = 16 mod 128
//    bytes -> conflict-free fragment loads.
//  - Same v9 structure: 128 CTAs x 512 thr, 8 m-pairs x 2 n-warps, pair-local
//    LN barriers, cp.async weight staging overlapped with rbf, tanh gelu.
// ---------------------------------------------------------------------------

namespace {
constexpr int B_TOT  = 16384;
constexpr int F      = 64;
constexpr int NB     = 64;
constexpr int H1     = 128;
constexpr int H2     = 128;
constexpr int TM     = 128;
constexpr int NTHR   = 512;
constexpr float LN_EPS = 1e-5f;

// u16-unit row strides (bytes = 2x; all ==16 mod 128 bytes)
constexpr int SA_R = 72;    // rbf [128][64+pad]  (144 B/row)
constexpr int SA_H = 136;   // hbuf [128][128+pad] (272 B/row)
constexpr int SB_1 = 72;    // W1t/Wrt [128][64+pad]
constexpr int SB_2 = 136;   // W2t [128][128+pad]

// byte offsets in dynamic smem
constexpr int B_W1T = 0;                       // 18432
constexpr int B_W2T = B_W1T + 128 * SB_1 * 2;  // 18432 .. +34816
constexpr int B_WRT = B_W2T + 128 * SB_2 * 2;  // 53248 .. +18432
constexpr int B_VEC = B_WRT + 128 * SB_1 * 2;  // 71680 (7*128 fp32)
constexpr int B_WSM = B_VEC + 7 * 128 * 4;     // 75264 (64 fp32)
constexpr int B_SCR = B_WSM + 256;             // 75520 (rbf/hbuf aliased)
constexpr int B_LNR = B_SCR + 128 * SA_H * 2;  // 110336 (float2[128][2])
constexpr int B_HRD = B_SCR;                   // head scratch aliases SCR
constexpr int SMEM_BYTES = B_LNR + 2048;       // 112384
}

__device__ __nv_bfloat16 g_w1t[F * H1 * NB];
__device__ __nv_bfloat16 g_w2t[F * H2 * H1];
__device__ __nv_bfloat16 g_wrt[F * H2 * NB];

// ---- prep: out[f][n][k] = bf16(in[f][k][n]), coalesced via smem tile ----
__global__ void transpose_prep(const float* __restrict__ in,
                               __nv_bfloat16* __restrict__ outp,
                               int K, int N) {
    __shared__ float ts[128 * 65];
    int f  = blockIdx.x / (N / 64);
    int nc = blockIdx.x % (N / 64);
    const float* src = in + (size_t)f * K * N + nc * 64;
    for (int idx = threadIdx.x; idx < K * 64; idx += 256) {
        int k = idx >> 6, n = idx & 63;
        ts[k * 65 + n] = src[(size_t)k * N + n];
    }
    __syncthreads();
    unsigned* dst = (unsigned*)(outp + (size_t)f * N * K);
    int khalf = K >> 1;
    for (int idx = threadIdx.x; idx < 64 * khalf; idx += 256) {
        int n = idx / khalf, kp = idx % khalf;
        float lo = ts[(2 * kp) * 65 + n];
        float hi = ts[(2 * kp + 1) * 65 + n];
        unsigned u;
        asm("cvt.rn.bf16x2.f32 %0, %1, %2;" : "=r"(u) : "f"(hi), "f"(lo));
        dst[(size_t)(nc * 64 + n) * khalf + kp] = u;
    }
}

__device__ __forceinline__ void mma16(float* d, const unsigned* a, unsigned b0, unsigned b1) {
    asm("mma.sync.aligned.m16n8k16.row.col.f32.bf16.bf16.f32 "
        "{%0,%1,%2,%3}, {%4,%5,%6,%7}, {%8,%9}, {%0,%1,%2,%3};"
        : "+f"(d[0]), "+f"(d[1]), "+f"(d[2]), "+f"(d[3])
        : "r"(a[0]), "r"(a[1]), "r"(a[2]), "r"(a[3]), "r"(b0), "r"(b1));
}

__device__ __forceinline__ unsigned pack_bf2(float lo, float hi) {
    unsigned u;
    asm("cvt.rn.bf16x2.f32 %0, %1, %2;" : "=r"(u) : "f"(hi), "f"(lo));
    return u;
}

__device__ __forceinline__ void cp16(unsigned dst, const void* src) {
    asm volatile("cp.async.cg.shared.global [%0], [%1], 16;" :: "r"(dst), "l"(src));
}

__device__ __forceinline__ float qred(float v) {
    v += __shfl_xor_sync(0xffffffffu, v, 1);
    v += __shfl_xor_sync(0xffffffffu, v, 2);
    return v;
}

__device__ __forceinline__ float gelu_fast(float v) {
    float z = 0.7978845608028654f * fmaf(0.044715f * v, v * v, v);
    float t;
    asm("tanh.approx.f32 %0, %1;" : "=f"(t) : "f"(z));
    return 0.5f * v * (1.0f + t);
}

__device__ __forceinline__ float softplus_f(float v) {
    return (v > 20.0f) ? v : log1pf(expf(v));
}

__device__ __forceinline__ float clipf(float v, float lo, float hi) {
    return fminf(fmaxf(v, lo), hi);
}

// acc[8][4] += A[16 x 16K] @ B^T (cols ncol0..+63); A,B bf16 in smem (u16 ptrs)
__device__ __forceinline__ void gemm16(float acc[8][4],
                                       const unsigned short* A, int sa,
                                       const unsigned short* B, int sb,
                                       int ksteps, int mrow0, int ncol0,
                                       int gid, int tidg) {
    for (int s = 0; s < ksteps; ++s) {
        int k0 = 16 * s + 2 * tidg;
        unsigned a[4];
        a[0] = *(const unsigned*)(A + (mrow0 + gid) * sa + k0);
        a[1] = *(const unsigned*)(A + (mrow0 + gid + 8) * sa + k0);
        a[2] = *(const unsigned*)(A + (mrow0 + gid) * sa + k0 + 8);
        a[3] = *(const unsigned*)(A + (mrow0 + gid + 8) * sa + k0 + 8);
        const unsigned short* bp = B + (ncol0 + gid) * sb + k0;
#pragma unroll
        for (int nt = 0; nt < 8; ++nt) {
            unsigned b0 = *(const unsigned*)(bp + 8 * nt * sb);
            unsigned b1 = *(const unsigned*)(bp + 8 * nt * sb + 8);
            mma16(acc[nt], a, b0, b1);
        }
    }
}

__global__ void __launch_bounds__(NTHR, 1)
nam_kernel(const float* __restrict__ x,        // [B,F]
           const float* __restrict__ centers,  // [F,NB]
           const float* __restrict__ logw,     // [F,NB]
           const __nv_bfloat16* __restrict__ w1t,  // [F][H1][NB]
           const __nv_bfloat16* __restrict__ w2t,  // [F][H2][H1]
           const __nv_bfloat16* __restrict__ wrt,  // [F][H2][NB]
           const float* __restrict__ b1,
           const float* __restrict__ g1,
           const float* __restrict__ be1,
           const float* __restrict__ b2,
           const float* __restrict__ g2,
           const float* __restrict__ be2,
           const float* __restrict__ br,
           const float* __restrict__ att,      // [F]
           const float* __restrict__ bias,     // [H2]
           const float* __restrict__ Wpi,      // [H2,3]
           const float* __restrict__ bpi,
           const float* __restrict__ Wa,
           const float* __restrict__ ba,
           const float* __restrict__ Wb,
           const float* __restrict__ bb,
           float* __restrict__ out)            // [B]
{
    extern __shared__ char smem[];
    unsigned short* W1T = (unsigned short*)(smem + B_W1T);
    unsigned short* W2T = (unsigned short*)(smem + B_W2T);
    unsigned short* WRT = (unsigned short*)(smem + B_WRT);
    float*  vecs = (float*)(smem + B_VEC);
    float*  w_s  = (float*)(smem + B_WSM);
    unsigned short* rbf_b  = (unsigned short*)(smem + B_SCR);  // [128][SA_R]
    unsigned short* hbuf_b = (unsigned short*)(smem + B_SCR);  // [128][SA_H] aliased
    float2* lnred = (float2*)(smem + B_LNR);
    float*  hred  = (float*)(smem + B_HRD);

    const int tid  = threadIdx.x;
    const int lane = tid & 31;
    const int wid  = tid >> 5;
    const int gid  = lane >> 2;
    const int tidg = lane & 3;
    const int mwid = wid & 7;
    const int nwid = wid >> 3;
    const int mrow0 = 16 * mwid;
    const int ncol0 = 64 * nwid;
    const int base_row = blockIdx.x * TM;
    const int bar_id = mwid + 1;

    const unsigned w1_sm = (unsigned)__cvta_generic_to_shared(W1T);
    const unsigned w2_sm = (unsigned)__cvta_generic_to_shared(W2T);
    const unsigned wr_sm = (unsigned)__cvta_generic_to_shared(WRT);

    if (tid < F) {
        float m = -1e30f;
        for (int i = 0; i < F; ++i) m = fmaxf(m, att[i]);
        float s = 0.0f;
        for (int i = 0; i < F; ++i) s += expf(att[i] - m);
        w_s[tid] = expf(att[tid] - m) / s;
    }

    float agg[8][4];
#pragma unroll
    for (int nt = 0; nt < 8; ++nt)
#pragma unroll
        for (int c = 0; c < 4; ++c) agg[nt][c] = 0.0f;

    for (int f = 0; f < F; ++f) {
        __syncthreads();

        // ---- stage pre-transposed bf16 weights (cp.async, padded rows) ----
        {
            const char* s1 = (const char*)(w1t + (size_t)f * H1 * NB);
            const char* s2 = (const char*)(w2t + (size_t)f * H2 * H1);
            const char* sr = (const char*)(wrt + (size_t)f * H2 * NB);
#pragma unroll
            for (int i = 0; i < 2; ++i) {       // W1t: 1024 granules
                int v = tid + i * NTHR;
                cp16(w1_sm + (v >> 3) * 144 + (v & 7) * 16, s1 + v * 16);
            }
#pragma unroll
            for (int i = 0; i < 4; ++i) {       // W2t: 2048 granules
                int v = tid + i * NTHR;
                cp16(w2_sm + (v >> 4) * 272 + (v & 15) * 16, s2 + v * 16);
            }
#pragma unroll
            for (int i = 0; i < 2; ++i) {       // Wrt: 1024 granules
                int v = tid + i * NTHR;
                cp16(wr_sm + (v >> 3) * 144 + (v & 7) * 16, sr + v * 16);
            }
            asm volatile("cp.async.commit_group;");
        }
        if (tid < 128) {
            vecs[tid]         = b1 [f * H1 + tid];
            vecs[128 + tid]   = g1 [f * H1 + tid];
            vecs[256 + tid]   = be1[f * H1 + tid];
            vecs[384 + tid]   = b2 [f * H2 + tid];
            vecs[512 + tid]   = g2 [f * H2 + tid];
            vecs[640 + tid]   = be2[f * H2 + tid];
            vecs[768 + tid]   = br [f * H2 + tid];
        }

        // ---- RBF (pair-local rows, bf16-packed store) ----
        {
            int n0 = lane * 2;
            float c0 = __ldg(centers + f * NB + n0);
            float c1 = __ldg(centers + f * NB + n0 + 1);
            float i0 = 1.0f / (expf(clipf(__ldg(logw + f * NB + n0),     -5.0f, 5.0f)) + 0.1f);
            float i1 = 1.0f / (expf(clipf(__ldg(logw + f * NB + n0 + 1), -5.0f, 5.0f)) + 0.1f);
            int r0 = mrow0 + 8 * nwid;
#pragma unroll
            for (int rr = 0; rr < 8; ++rr) {
                int row = r0 + rr;
                float xv = clipf(__ldg(x + (size_t)(base_row + row) * F + f), -10.0f, 10.0f);
                float d0 = clipf((xv - c0) * i0, -10.0f, 10.0f);
                float d1v = clipf((xv - c1) * i1, -10.0f, 10.0f);
                float e0 = __expf(-0.5f * d0 * d0);
                float e1 = __expf(-0.5f * d1v * d1v);
                *(unsigned*)(rbf_b + row * SA_R + n0) = pack_bf2(e0, e1);
            }
        }

        asm volatile("cp.async.wait_group 0;" ::: "memory");
        __syncthreads();

        float acc[8][4];

        // ---- G3: res = rbf @ Wr^T ; fold into agg ----
#pragma unroll
        for (int nt = 0; nt < 8; ++nt)
#pragma unroll
            for (int c = 0; c < 4; ++c) acc[nt][c] = 0.0f;
        gemm16(acc, rbf_b, SA_R, WRT, SB_1, NB / 16, mrow0, ncol0, gid, tidg);
        {
            float wf01 = 0.1f * w_s[f];
#pragma unroll
            for (int nt = 0; nt < 8; ++nt) {
                int c = ncol0 + 8 * nt + 2 * tidg;
                float2 brv = *(const float2*)(vecs + 768 + c);
                agg[nt][0] += wf01 * (acc[nt][0] + brv.x);
                agg[nt][1] += wf01 * (acc[nt][1] + brv.y);
                agg[nt][2] += wf01 * (acc[nt][2] + brv.x);
                agg[nt][3] += wf01 * (acc[nt][3] + brv.y);
            }
        }

        // ---- G1: h1 = rbf @ W1^T ----
#pragma unroll
        for (int nt = 0; nt < 8; ++nt)
#pragma unroll
            for (int c = 0; c < 4; ++c) acc[nt][c] = 0.0f;
        gemm16(acc, rbf_b, SA_R, W1T, SB_1, NB / 16, mrow0, ncol0, gid, tidg);

        // ---- LN1 + gelu -> hbuf (bf16, pair-scoped) ----
        {
            float sum0 = 0.f, sq0 = 0.f, sum1 = 0.f, sq1 = 0.f;
#pragma unroll
            for (int nt = 0; nt < 8; ++nt) {
                int c = ncol0 + 8 * nt + 2 * tidg;
                float2 bv = *(const float2*)(vecs + c);
                float v0 = acc[nt][0] + bv.x, v1 = acc[nt][1] + bv.y;
                float v2 = acc[nt][2] + bv.x, v3 = acc[nt][3] + bv.y;
                acc[nt][0] = v0; acc[nt][1] = v1; acc[nt][2] = v2; acc[nt][3] = v3;
                sum0 += v0 + v1; sq0 += v0 * v0 + v1 * v1;
                sum1 += v2 + v3; sq1 += v2 * v2 + v3 * v3;
            }
            sum0 = qred(sum0); sq0 = qred(sq0);
            sum1 = qred(sum1); sq1 = qred(sq1);
            int row0 = mrow0 + gid;
            if (tidg == 0) {
                lnred[row0 * 2 + nwid]       = make_float2(sum0, sq0);
                lnred[(row0 + 8) * 2 + nwid] = make_float2(sum1, sq1);
            }
            asm volatile("bar.sync %0, 64;" :: "r"(bar_id) : "memory");
            float2 p0 = lnred[row0 * 2 + (1 - nwid)];
            float2 p1 = lnred[(row0 + 8) * 2 + (1 - nwid)];
            float mu0 = (sum0 + p0.x) * (1.0f / H1);
            float mu1 = (sum1 + p1.x) * (1.0f / H1);
            float in0 = rsqrtf((sq0 + p0.y) * (1.0f / H1) - mu0 * mu0 + LN_EPS);
            float in1 = rsqrtf((sq1 + p1.y) * (1.0f / H1) - mu1 * mu1 + LN_EPS);
#pragma unroll
            for (int nt = 0; nt < 8; ++nt) {
                int c = ncol0 + 8 * nt + 2 * tidg;
                float2 gv  = *(const float2*)(vecs + 128 + c);
                float2 bev = *(const float2*)(vecs + 256 + c);
                float h0 = gelu_fast((acc[nt][0] - mu0) * in0 * gv.x + bev.x);
                float h1 = gelu_fast((acc[nt][1] - mu0) * in0 * gv.y + bev.y);
                float h2 = gelu_fast((acc[nt][2] - mu1) * in1 * gv.x + bev.x);
                float h3 = gelu_fast((acc[nt][3] - mu1) * in1 * gv.y + bev.y);
                *(unsigned*)(hbuf_b + row0 * SA_H + c)       = pack_bf2(h0, h1);
                *(unsigned*)(hbuf_b + (row0 + 8) * SA_H + c) = pack_bf2(h2, h3);
            }
        }
        asm volatile("bar.sync %0, 64;" :: "r"(bar_id) : "memory");

        // ---- G2: h2pre = h @ W2^T ----
#pragma unroll
        for (int nt = 0; nt < 8; ++nt)
#pragma unroll
            for (int c = 0; c < 4; ++c) acc[nt][c] = 0.0f;
        gemm16(acc, hbuf_b, SA_H, W2T, SB_2, H1 / 16, mrow0, ncol0, gid, tidg);

        // ---- LN2 + gelu; agg += wf * h2 (pair-scoped) ----
        {
            float sum0 = 0.f, sq0 = 0.f, sum1 = 0.f, sq1 = 0.f;
#pragma unroll
            for (int nt = 0; nt < 8; ++nt) {
                int c = ncol0 + 8 * nt + 2 * tidg;
                float2 bv = *(const float2*)(vecs + 384 + c);
                float v0 = acc[nt][0] + bv.x, v1 = acc[nt][1] + bv.y;
                float v2 = acc[nt][2] + bv.x, v3 = acc[nt][3] + bv.y;
                acc[nt][0] = v0; acc[nt][1] = v1; acc[nt][2] = v2; acc[nt][3] = v3;
                sum0 += v0 + v1; sq0 += v0 * v0 + v1 * v1;
                sum1 += v2 + v3; sq1 += v2 * v2 + v3 * v3;
            }
            sum0 = qred(sum0); sq0 = qred(sq0);
            sum1 = qred(sum1); sq1 = qred(sq1);
            int row0 = mrow0 + gid;
            if (tidg == 0) {
                lnred[row0 * 2 + nwid]       = make_float2(sum0, sq0);
                lnred[(row0 + 8) * 2 + nwid] = make_float2(sum1, sq1);
            }
            asm volatile("bar.sync %0, 64;" :: "r"(bar_id) : "memory");
            float2 p0 = lnred[row0 * 2 + (1 - nwid)];
            float2 p1 = lnred[(row0 + 8) * 2 + (1 - nwid)];
            float mu0 = (sum0 + p0.x) * (1.0f / H2);
            float mu1 = (sum1 + p1.x) * (1.0f / H2);
            float in0 = rsqrtf((sq0 + p0.y) * (1.0f / H2) - mu0 * mu0 + LN_EPS);
            float in1 = rsqrtf((sq1 + p1.y) * (1.0f / H2) - mu1 * mu1 + LN_EPS);
            float wf = w_s[f];
#pragma unroll
            for (int nt = 0; nt < 8; ++nt) {
                int c = ncol0 + 8 * nt + 2 * tidg;
                float2 gv  = *(const float2*)(vecs + 512 + c);
                float2 bev = *(const float2*)(vecs + 640 + c);
                agg[nt][0] += wf * gelu_fast((acc[nt][0] - mu0) * in0 * gv.x + bev.x);
                agg[nt][1] += wf * gelu_fast((acc[nt][1] - mu0) * in0 * gv.y + bev.y);
                agg[nt][2] += wf * gelu_fast((acc[nt][2] - mu1) * in1 * gv.x + bev.x);
                agg[nt][3] += wf * gelu_fast((acc[nt][3] - mu1) * in1 * gv.y + bev.y);
            }
        }
    }

    // ---- head (exact math) ----
    __syncthreads();   // scratch (hred alias) free; all pairs done
    {
        int row0 = mrow0 + gid;
        float P[9], Q[9];
#pragma unroll
        for (int q = 0; q < 9; ++q) { P[q] = 0.f; Q[q] = 0.f; }
#pragma unroll
        for (int nt = 0; nt < 8; ++nt) {
            int c = ncol0 + 8 * nt + 2 * tidg;
            float bs0 = __ldg(bias + c), bs1 = __ldg(bias + c + 1);
            float a0 = agg[nt][0] + bs0, a1 = agg[nt][1] + bs1;
            float a2 = agg[nt][2] + bs0, a3 = agg[nt][3] + bs1;
#pragma unroll
            for (int j = 0; j < 3; ++j) {
                float wp0 = __ldg(Wpi + c * 3 + j), wp1 = __ldg(Wpi + (c + 1) * 3 + j);
                float wa0 = __ldg(Wa  + c * 3 + j), wa1 = __ldg(Wa  + (c + 1) * 3 + j);
                float wb0 = __ldg(Wb  + c * 3 + j), wb1 = __ldg(Wb  + (c + 1) * 3 + j);
                P[j]     += a0 * wp0 + a1 * wp1;  Q[j]     += a2 * wp0 + a3 * wp1;
                P[3 + j] += a0 * wa0 + a1 * wa1;  Q[3 + j] += a2 * wa0 + a3 * wa1;
                P[6 + j] += a0 * wb0 + a1 * wb1;  Q[6 + j] += a2 * wb0 + a3 * wb1;
            }
        }
#pragma unroll
        for (int q = 0; q < 9; ++q) { P[q] = qred(P[q]); Q[q] = qred(Q[q]); }

        if (nwid == 1 && tidg == 0) {
#pragma unroll
            for (int q = 0; q < 9; ++q) {
                hred[row0 * 9 + q]       = P[q];
                hred[(row0 + 8) * 9 + q] = Q[q];
            }
        }
        asm volatile("bar.sync %0, 64;" :: "r"(bar_id) : "memory");
        if (nwid == 0 && tidg == 0) {
#pragma unroll
            for (int half = 0; half < 2; ++half) {
                int row = row0 + 8 * half;
                float* S = half ? Q : P;
                float s0 = S[0] + hred[row * 9 + 0];
                float s1 = S[1] + hred[row * 9 + 1];
                float s2 = S[2] + hred[row * 9 + 2];
                float A0 = S[3] + hred[row * 9 + 3];
                float A1 = S[4] + hred[row * 9 + 4];
                float A2 = S[5] + hred[row * 9 + 5];
                float C0 = S[6] + hred[row * 9 + 6];
                float C1 = S[7] + hred[row * 9 + 7];
                float C2 = S[8] + hred[row * 9 + 8];
                float l0 = s0 + __ldg(bpi + 0);
                float l1 = s1 + __ldg(bpi + 1);
                float l2 = s2 + __ldg(bpi + 2);
                float m = fmaxf(l0, fmaxf(l1, l2));
                float e0 = expf(l0 - m), e1 = expf(l1 - m), e2 = expf(l2 - m);
                float inv_es = 1.0f / (e0 + e1 + e2);
                float ak0 = clipf(softplus_f(A0 + __ldg(ba + 0)) + 1.01f, 1.01f, 100.0f);
                float ak1 = clipf(softplus_f(A1 + __ldg(ba + 1)) + 1.01f, 1.01f, 100.0f);
                float ak2 = clipf(softplus_f(A2 + __ldg(ba + 2)) + 1.01f, 1.01f, 100.0f);
                float bk0 = clipf(softplus_f(C0 + __ldg(bb + 0)) + 1.01f, 1.01f, 100.0f);
                float bk1 = clipf(softplus_f(C1 + __ldg(bb + 1)) + 1.01f, 1.01f, 100.0f);
                float bk2 = clipf(softplus_f(C2 + __ldg(bb + 2)) + 1.01f, 1.01f, 100.0f);
                float pred = (e0 * inv_es) * (ak0 / (ak0 + bk0))
                           + (e1 * inv_es) * (ak1 / (ak1 + bk1))
                           + (e2 * inv_es) * (ak2 / (ak2 + bk2));
                out[base_row + row] = clipf(pred, 0.001f, 0.999f);
            }
        }
    }
}

extern "C" void kernel_launch(void* const* d_in, const int* in_sizes, int n_in,
                              void* d_out, int out_size) {
    (void)in_sizes; (void)n_in; (void)out_size;
    cudaFuncSetAttribute(nam_kernel,
                         cudaFuncAttributeMaxDynamicSharedMemorySize, SMEM_BYTES);
    const float* x       = (const float*)d_in[0];
    const float* centers = (const float*)d_in[1];
    const float* logw    = (const float*)d_in[2];
    const float* W1      = (const float*)d_in[3];
    const float* b1      = (const float*)d_in[4];
    const float* g1      = (const float*)d_in[5];
    const float* be1     = (const float*)d_in[6];
    const float* W2      = (const float*)d_in[7];
    const float* b2      = (const float*)d_in[8];
    const float* g2      = (const float*)d_in[9];
    const float* be2     = (const float*)d_in[10];
    const float* Wr      = (const float*)d_in[11];
    const float* br      = (const float*)d_in[12];
    const float* att     = (const float*)d_in[13];
    const float* bias    = (const float*)d_in[14];
    const float* Wpi     = (const float*)d_in[15];
    const float* bpi     = (const float*)d_in[16];
    const float* Wa      = (const float*)d_in[17];
    const float* ba      = (const float*)d_in[18];
    const float* Wb      = (const float*)d_in[19];
    const float* bb      = (const float*)d_in[20];
    float* out = (float*)d_out;

    void *p1, *p2, *p3;
    cudaGetSymbolAddress(&p1, g_w1t);
    cudaGetSymbolAddress(&p2, g_w2t);
    cudaGetSymbolAddress(&p3, g_wrt);

    transpose_prep<<<F * (H1 / 64), 256>>>(W1, (__nv_bfloat16*)p1, NB, H1);
    transpose_prep<<<F * (H2 / 64), 256>>>(W2, (__nv_bfloat16*)p2, H1, H2);
    transpose_prep<<<F * (H2 / 64), 256>>>(Wr, (__nv_bfloat16*)p3, NB, H2);

    nam_kernel<<<B_TOT / TM, NTHR, SMEM_BYTES>>>(
        x, centers, logw,
        (const __nv_bfloat16*)p1, (const __nv_bfloat16*)p2, (const __nv_bfloat16*)p3,
        b1, g1, be1, b2, g2, be2, br,
        att, bias, Wpi, bpi, Wa, ba, Wb, bb, out);
}